// round 12
// baseline (speedup 1.0000x reference)
#include <cuda_runtime.h>
#include <cuda_fp16.h>
#include <math.h>

#define BB   64
#define SS   512
#define HH   1024
#define G4   4096
#define NCTA 128
#define KC   64
#define NCH  16
#define PK   72
#define PK2  1032
#define KA   640

typedef unsigned int u32;

__device__ float g_P0[BB * SS * G4];
__device__ float g_P1[BB * SS * G4];
__device__ float g_Hout[BB * SS * HH];
__device__ __half g_Wt[3ULL * G4 * HH];   // recur weights [mat][col][k]
__device__ __half g_A[BB * SS * KA];      // [r][640] = [x|z] fp16
__device__ __half g_B0[G4 * KA];          // [n][640] = [W0|V0]^T fp16
__device__ __half g_B1[G4 * 128];         // [n][128] = V1^T fp16
__device__ __half g_h0[2][BB * HH];
__device__ __half g_h1[2][BB * HH];
__device__ unsigned g_bar;

__device__ __forceinline__ float4 ldg4(const float* p)  { return __ldg((const float4*)p); }
__device__ __forceinline__ float sigf(float x)  { return 1.0f / (1.0f + __expf(-x)); }
__device__ __forceinline__ float tanha(float x) { return 1.0f - 2.0f / (__expf(2.0f * x) + 1.0f); }

__device__ __forceinline__ void mma_h(float* c, u32 a0, u32 a1, u32 a2, u32 a3,
                                      u32 b0, u32 b1)
{
    asm volatile(
        "mma.sync.aligned.m16n8k16.row.col.f32.f16.f16.f32 "
        "{%0,%1,%2,%3}, {%4,%5,%6,%7}, {%8,%9}, {%0,%1,%2,%3};\n"
        : "+f"(c[0]), "+f"(c[1]), "+f"(c[2]), "+f"(c[3])
        : "r"(a0), "r"(a1), "r"(a2), "r"(a3), "r"(b0), "r"(b1));
}
__device__ __forceinline__ void ldsm4(u32& r0, u32& r1, u32& r2, u32& r3, u32 a)
{
    asm volatile("ldmatrix.sync.aligned.m8n8.x4.shared.b16 {%0,%1,%2,%3}, [%4];\n"
                 : "=r"(r0), "=r"(r1), "=r"(r2), "=r"(r3) : "r"(a));
}
__device__ __forceinline__ void cpa16(void* dst, const void* src) {
    u32 d = (u32)__cvta_generic_to_shared(dst);
    asm volatile("cp.async.cg.shared.global [%0], [%1], 16;\n" :: "r"(d), "l"(src));
}
__device__ __forceinline__ void cpa16u(u32 dst, const void* src) {
    asm volatile("cp.async.cg.shared.global [%0], [%1], 16;\n" :: "r"(dst), "l"(src));
}
#define CP_COMMIT() asm volatile("cp.async.commit_group;\n" ::: "memory")

// ---------------- prep2a + init (merged) -------------------------------------
__global__ void __launch_bounds__(256)
prep2a_kernel(const float* __restrict__ x, const float* __restrict__ z)
{
    size_t gtid = (size_t)blockIdx.x * blockDim.x + threadIdx.x;
    size_t stride = (size_t)gridDim.x * blockDim.x;
    __half hz = __float2half(0.f);
    for (size_t i = gtid; i < BB * HH; i += stride) {
        g_h0[0][i] = hz; g_h0[1][i] = hz;
        g_h1[0][i] = hz; g_h1[1][i] = hz;
    }
    if (gtid == 0) g_bar = 0u;
    size_t total = (size_t)BB * SS * KA;
    for (size_t idx = gtid; idx < total; idx += stride) {
        size_t r = idx / KA;
        int k = (int)(idx - r * KA);
        float v = (k < 512) ? __ldg(&x[r * 512 + k]) : __ldg(&z[r * 128 + (k - 512)]);
        g_A[idx] = __float2half(v);
    }
}

// ---------------- prep_all (merged transpose kernels) ------------------------
__global__ void __launch_bounds__(256)
prep_all_kernel(const float* __restrict__ U0, const float* __restrict__ W1,
                const float* __restrict__ U1, const float* __restrict__ W0,
                const float* __restrict__ V0, const float* __restrict__ V1)
{
    int zi = blockIdx.z;
    __shared__ float tile[64][65];
    int tid = threadIdx.x;
    if (zi < 3) {
        const float* src = (zi == 0) ? U0 : ((zi == 1) ? W1 : U1);
        int c0 = blockIdx.x * 64;
        int k0 = blockIdx.y * 64;
#pragma unroll
        for (int i = 0; i < 4; ++i) {
            int lin = tid + i * 256;
            int kr = lin >> 4, cq = lin & 15;
            float4 v = ldg4(src + (size_t)(k0 + kr) * G4 + c0 + cq * 4);
            tile[kr][cq * 4 + 0] = v.x; tile[kr][cq * 4 + 1] = v.y;
            tile[kr][cq * 4 + 2] = v.z; tile[kr][cq * 4 + 3] = v.w;
        }
        __syncthreads();
#pragma unroll
        for (int i = 0; i < 2; ++i) {
            int lin = tid + i * 256;
            int cr = lin >> 3, seg = (lin & 7) * 8;
            __half tmp[8];
#pragma unroll
            for (int j = 0; j < 8; ++j) tmp[j] = __float2half(tile[seg + j][cr]);
            *(uint4*)(g_Wt + ((size_t)zi * G4 + c0 + cr) * HH + k0 + seg) = *(uint4*)tmp;
        }
        return;
    }
    int which = zi - 3;
    if (which == 0) { if (blockIdx.y >= 8) return; }
    else            { if (blockIdx.y >= 2) return; }
    const float* W = (which == 0) ? W0 : ((which == 1) ? V0 : V1);
    int n0 = blockIdx.x * 64;
    int k0 = blockIdx.y * 64;
#pragma unroll
    for (int i = 0; i < 4; ++i) {
        int lin = tid + i * 256;
        int kr = lin >> 4, nq = lin & 15;
        float4 v = ldg4(W + (size_t)(k0 + kr) * G4 + n0 + nq * 4);
        tile[kr][nq * 4 + 0] = v.x; tile[kr][nq * 4 + 1] = v.y;
        tile[kr][nq * 4 + 2] = v.z; tile[kr][nq * 4 + 3] = v.w;
    }
    __syncthreads();
    __half* dst; int ldb, kb;
    if (which == 0)      { dst = g_B0; ldb = KA;  kb = k0; }
    else if (which == 1) { dst = g_B0; ldb = KA;  kb = 512 + k0; }
    else                 { dst = g_B1; ldb = 128; kb = k0; }
#pragma unroll
    for (int i = 0; i < 2; ++i) {
        int lin = tid + i * 256;
        int nr = lin >> 3, seg = (lin & 7) * 8;
        __half th[8];
#pragma unroll
        for (int j = 0; j < 8; ++j) th[j] = __float2half(tile[seg + j][nr]);
        *(uint4*)(dst + (size_t)(n0 + nr) * ldb + kb + seg) = *(uint4*)th;
    }
}

// ---------------- precompute GEMM: fp16 single-term --------------------------
struct GSmem {
    __half A[3][64][PK];
    __half B[3][64][PK];
};
#define G_SMEM_BYTES ((int)sizeof(GSmem))

__global__ void __launch_bounds__(256, 2)
gemm_mma_kernel(const float* __restrict__ bsA1, const float* __restrict__ bsA2,
                const float* __restrict__ bsB1, const float* __restrict__ bsB2)
{
    const int which = blockIdx.z;
    const __half* __restrict__ A; const __half* __restrict__ B;
    const float* bs1; const float* bs2;
    int ldb, K; float* OUT;
    if (which == 0) { A = g_A;       B = g_B0; ldb = KA;  K = KA;  OUT = g_P0; bs1 = bsA1; bs2 = bsA2; }
    else            { A = g_A + 512; B = g_B1; ldb = 128; K = 128; OUT = g_P1; bs1 = bsB1; bs2 = bsB2; }
    const int lda = KA;

    extern __shared__ unsigned char smraw[];
    GSmem* sm = (GSmem*)smraw;
    const int tid = threadIdx.x;
    const int n0 = blockIdx.x * 64;
    const int m0 = blockIdx.y * 64;
    const int lane = tid & 31, w = tid >> 5;
    const int g = lane >> 2, q2 = (lane & 3) * 2;
    const int lg = lane >> 3, lr = lane & 7;
    const int wm = (w >> 2) * 32;
    const int wn = (w & 3) * 16;
    const int nch = K / KC;

    const int l0 = tid * 2, l1 = tid * 2 + 1;
    const int ar0 = l0 >> 3, as0 = (l0 & 7) * 8;
    const int ar1 = l1 >> 3, as1 = (l1 & 7) * 8;

    const u32 bufstr = 64 * PK * 2;
    const u32 baseA = (u32)__cvta_generic_to_shared(&sm->A[0][0][0]);
    const u32 baseB = (u32)__cvta_generic_to_shared(&sm->B[0][0][0]);
    const u32 offA0 = (u32)(wm + (lg & 1) * 8 + lr) * (PK * 2) + (lg >> 1) * 16;
    const u32 offA1 = offA0 + 16 * (PK * 2);
    const u32 offB  = (u32)(wn + (lg >> 1) * 8 + lr) * (PK * 2) + (lg & 1) * 16;

    float acc[2][2][4];
#pragma unroll
    for (int a = 0; a < 2; ++a)
#pragma unroll
        for (int b = 0; b < 2; ++b)
#pragma unroll
            for (int c = 0; c < 4; ++c) acc[a][b][c] = 0.f;

#pragma unroll
    for (int pc = 0; pc < 2; ++pc) {
        int k0 = pc * KC;
        cpa16(&sm->A[pc][ar0][as0], A + (size_t)(m0 + ar0) * lda + k0 + as0);
        cpa16(&sm->A[pc][ar1][as1], A + (size_t)(m0 + ar1) * lda + k0 + as1);
        cpa16(&sm->B[pc][ar0][as0], B + (size_t)(n0 + ar0) * ldb + k0 + as0);
        cpa16(&sm->B[pc][ar1][as1], B + (size_t)(n0 + ar1) * ldb + k0 + as1);
        CP_COMMIT();
    }

    for (int ch = 0; ch < nch; ++ch) {
        if (ch < nch - 1) asm volatile("cp.async.wait_group 1;\n" ::: "memory");
        else              asm volatile("cp.async.wait_group 0;\n" ::: "memory");
        __syncthreads();
        if (ch + 2 < nch) {
            int buf = (ch + 2) % 3;
            int k0 = (ch + 2) * KC;
            cpa16(&sm->A[buf][ar0][as0], A + (size_t)(m0 + ar0) * lda + k0 + as0);
            cpa16(&sm->A[buf][ar1][as1], A + (size_t)(m0 + ar1) * lda + k0 + as1);
            cpa16(&sm->B[buf][ar0][as0], B + (size_t)(n0 + ar0) * ldb + k0 + as0);
            cpa16(&sm->B[buf][ar1][as1], B + (size_t)(n0 + ar1) * ldb + k0 + as1);
            CP_COMMIT();
        }
        const int buf = ch % 3;
        const u32 bo = buf * bufstr;
#pragma unroll
        for (int kk = 0; kk < 4; ++kk) {
            const u32 kb2 = kk * 32;
            u32 a[2][4], b[4];
            ldsm4(a[0][0], a[0][1], a[0][2], a[0][3], baseA + bo + offA0 + kb2);
            ldsm4(a[1][0], a[1][1], a[1][2], a[1][3], baseA + bo + offA1 + kb2);
            ldsm4(b[0], b[1], b[2], b[3], baseB + bo + offB + kb2);
#pragma unroll
            for (int nt = 0; nt < 2; ++nt)
#pragma unroll
                for (int mt = 0; mt < 2; ++mt)
                    mma_h(acc[mt][nt], a[mt][0], a[mt][1], a[mt][2], a[mt][3],
                          b[nt * 2], b[nt * 2 + 1]);
        }
    }

#pragma unroll
    for (int mt = 0; mt < 2; ++mt) {
        int r0 = m0 + wm + mt * 16 + g;
#pragma unroll
        for (int nt = 0; nt < 2; ++nt) {
            int c = n0 + wn + nt * 8 + q2;
            float b0 = __ldg(&bs1[c]) + __ldg(&bs2[c]);
            float b1 = __ldg(&bs1[c + 1]) + __ldg(&bs2[c + 1]);
            OUT[(size_t)r0 * G4 + c]           = acc[mt][nt][0] + b0;
            OUT[(size_t)r0 * G4 + c + 1]       = acc[mt][nt][1] + b1;
            OUT[(size_t)(r0 + 8) * G4 + c]     = acc[mt][nt][2] + b0;
            OUT[(size_t)(r0 + 8) * G4 + c + 1] = acc[mt][nt][3] + b1;
        }
    }
}

__device__ __forceinline__ void gbar(unsigned& epoch)
{
    __syncthreads();
    epoch += NCTA;
    if (threadIdx.x == 0) {
        __threadfence();
        atomicAdd(&g_bar, 1u);
        while (*(volatile unsigned*)&g_bar < epoch) { }
        __threadfence();
    }
    __syncthreads();
}

// ---------------- recurrent: 384 threads, balanced warps ---------------------
// warps 0-7: h0 @ [W1|U0]  (64x64), each m32 x n16
// warps 8-11: h1 @ U1 (resident, 64x32), each m32 x n16
struct RecSmem {
    __half A1[4][64][PK];
    __half A2[4][64][PK];
    __half B1[4][64][PK];     // streamed [W1 | U0] slice
    __half B2r[32][PK2];      // resident U1 slice
    float pre1[32][66];
    float pre0[32][66];
    float c0[8][66];
    float c1[8][66];
};
#define REC_SMEM_BYTES ((int)sizeof(RecSmem))
#define RTH 384

__global__ void __launch_bounds__(RTH, 1)
recur_kernel(float* __restrict__ out)
{
    extern __shared__ unsigned char smraw[];
    RecSmem* sm = (RecSmem*)smraw;

    const int tid = threadIdx.x;
    const int u0 = blockIdx.x * 8;
    const int lane = tid & 31, w = tid >> 5;
    const int g = lane >> 2, q2 = (lane & 3) * 2;
    const int lg = lane >> 3, lr = lane & 7;
    const int cu = tid & 7, cb = tid >> 3;

    // ---- staging map: 4 lines/thread over [A1(512) | A2(512) | B1(512)] ----
    int kindv[4]; size_t offG[4]; const __half* srcC[4]; u32 dstA[4];
    const u32 baseA1 = (u32)__cvta_generic_to_shared(&sm->A1[0][0][0]);
    const u32 baseA2 = (u32)__cvta_generic_to_shared(&sm->A2[0][0][0]);
    const u32 baseB1 = (u32)__cvta_generic_to_shared(&sm->B1[0][0][0]);
    const u32 baseB2 = (u32)__cvta_generic_to_shared(&sm->B2r[0][0]);
#pragma unroll
    for (int i = 0; i < 4; ++i) {
        int lin = tid + i * RTH;
        int kind = lin >> 9;
        int local = lin & 511;
        int row = local >> 3, sg = (local & 7) * 8;
        kindv[i] = kind;
        offG[i] = (size_t)row * HH + sg;
        srcC[i] = 0;
        if (kind == 2) {
            int jj = row & 31;
            int mat = (row < 32) ? 1 : 0;
            srcC[i] = g_Wt + ((size_t)mat * G4 + ((size_t)(jj >> 3) << 10) + u0 + (jj & 7)) * HH + sg;
        }
        u32 base = (kind == 0) ? baseA1 : ((kind == 1) ? baseA2 : baseB1);
        dstA[i] = base + (u32)row * (PK * 2) + (u32)sg * 2;
    }

    // ---- compute map (all warps: m32 x n16, acc[2][2][4]) ----
    const bool g1 = (w < 8);
    const int wl = g1 ? w : (w - 8);
    const int wm = g1 ? ((w >> 2) * 32) : ((wl >> 1) * 32);
    const int wn = g1 ? ((w & 3) * 16) : ((wl & 1) * 16);
    const u32 baseAx = g1 ? baseA1 : baseA2;
    const u32 offA_0 = (u32)(wm + (lg & 1) * 8 + lr) * (PK * 2) + (lg >> 1) * 16;
    const u32 offA_1 = offA_0 + 16 * (PK * 2);
    const u32 offB = g1
        ? (u32)(wn + (lg >> 1) * 8 + lr) * (PK * 2) + (lg & 1) * 16
        : (u32)(wn + (lg >> 1) * 8 + lr) * (PK2 * 2) + (lg & 1) * 16;
    const u32 bufstr = 64 * PK * 2;

    // ---- resident U1 slice ----
    for (int lin = tid; lin < 4096; lin += RTH) {
        int row = lin >> 7, seg = (lin & 127) * 8;
        size_t c = ((size_t)2 * G4 + ((row >> 3) << 10) + u0 + (row & 7));
        *(uint4*)&sm->B2r[row][seg] = *(const uint4*)(g_Wt + c * HH + seg);
    }
    for (int i = tid; i < 8 * 66; i += RTH) {
        ((float*)sm->c0)[i] = 0.f;
        ((float*)sm->c1)[i] = 0.f;
    }
    __syncthreads();
    if (tid < 256) {
#pragma unroll
        for (int half = 0; half < 2; ++half) {
            int b = cb + half * 32;
            size_t base = ((size_t)b * SS) * G4 + u0 + cu;
            float pi = g_P0[base + 1024];
            float pg = g_P0[base + 2048];
            float po = g_P0[base + 3072];
            float cn = sigf(pi) * tanha(pg);
            sm->c0[cu][b] = cn;
            g_h0[0][b * HH + u0 + cu] = __float2half(sigf(po) * tanha(cn));
        }
    }
    unsigned epoch = 0;
    gbar(epoch);

    for (int t = 0; t < SS; ++t) {
        const __half* h0r = g_h0[t & 1];
        const __half* h1r = g_h1[(t + 1) & 1];
        __half* h0w = g_h0[(t + 1) & 1];
        __half* h1w = g_h1[t & 1];

        float acc[2][2][4];
#pragma unroll
        for (int a = 0; a < 2; ++a)
#pragma unroll
            for (int b = 0; b < 2; ++b)
#pragma unroll
                for (int c = 0; c < 4; ++c) acc[a][b][c] = 0.f;

#pragma unroll
        for (int pc = 0; pc < 3; ++pc) {
            int kc = pc * KC;
#pragma unroll
            for (int i = 0; i < 4; ++i) {
                const __half* s = (kindv[i] == 0) ? (h0r + offG[i])
                                 : (kindv[i] == 1) ? (h1r + offG[i]) : srcC[i];
                cpa16u(dstA[i] + pc * bufstr, s + kc);
            }
            CP_COMMIT();
        }

        for (int ch = 0; ch < NCH; ++ch) {
            if (ch <= NCH - 3)      asm volatile("cp.async.wait_group 2;\n" ::: "memory");
            else if (ch == NCH - 2) asm volatile("cp.async.wait_group 1;\n" ::: "memory");
            else                    asm volatile("cp.async.wait_group 0;\n" ::: "memory");
            __syncthreads();
            if (ch + 3 < NCH) {
                int buf = (ch + 3) & 3;
                int kc = (ch + 3) * KC;
#pragma unroll
                for (int i = 0; i < 4; ++i) {
                    const __half* s = (kindv[i] == 0) ? (h0r + offG[i])
                                     : (kindv[i] == 1) ? (h1r + offG[i]) : srcC[i];
                    cpa16u(dstA[i] + buf * bufstr, s + kc);
                }
                CP_COMMIT();
            }
            const int buf = ch & 3;
            const u32 bo = buf * bufstr;
            const u32 kgl2 = (u32)(ch * KC) * 2;
#pragma unroll
            for (int kk = 0; kk < 4; ++kk) {
                const u32 kb2 = kk * 32;
                u32 a[2][4], b[4];
                ldsm4(a[0][0], a[0][1], a[0][2], a[0][3], baseAx + bo + offA_0 + kb2);
                ldsm4(a[1][0], a[1][1], a[1][2], a[1][3], baseAx + bo + offA_1 + kb2);
                if (g1) ldsm4(b[0], b[1], b[2], b[3], baseB1 + bo + offB + kb2);
                else    ldsm4(b[0], b[1], b[2], b[3], baseB2 + offB + kgl2 + kb2);
#pragma unroll
                for (int nt = 0; nt < 2; ++nt)
#pragma unroll
                    for (int mt = 0; mt < 2; ++mt)
                        mma_h(acc[mt][nt], a[mt][0], a[mt][1], a[mt][2], a[mt][3],
                              b[nt * 2], b[nt * 2 + 1]);
            }
        }
        __syncthreads();

        // ---- epilogue stage 1: warps 0-7 write pre1 (+P1) / pre0 (+P0) ----
        if (w < 8) {
            const bool isL1 = (wn < 32);
#pragma unroll
            for (int mt = 0; mt < 2; ++mt) {
                int r0 = wm + mt * 16 + g;
#pragma unroll
                for (int nt = 0; nt < 2; ++nt) {
                    int cj = (wn & 31) + nt * 8 + q2;
                    int gate = cj >> 3, un = cj & 7;
                    if (isL1) {
                        const float* base = g_P1 + ((size_t)gate << 10) + u0 + un;
                        float2 pa = *(const float2*)(base + ((size_t)r0 * SS + t) * G4);
                        float2 pb = *(const float2*)(base + ((size_t)(r0 + 8) * SS + t) * G4);
                        sm->pre1[cj][r0]         = acc[mt][nt][0] + pa.x;
                        sm->pre1[cj + 1][r0]     = acc[mt][nt][1] + pa.y;
                        sm->pre1[cj][r0 + 8]     = acc[mt][nt][2] + pb.x;
                        sm->pre1[cj + 1][r0 + 8] = acc[mt][nt][3] + pb.y;
                    } else if (t < SS - 1) {
                        const float* base = g_P0 + ((size_t)gate << 10) + u0 + un;
                        float2 pa = *(const float2*)(base + ((size_t)r0 * SS + t + 1) * G4);
                        float2 pb = *(const float2*)(base + ((size_t)(r0 + 8) * SS + t + 1) * G4);
                        sm->pre0[cj][r0]         = acc[mt][nt][0] + pa.x;
                        sm->pre0[cj + 1][r0]     = acc[mt][nt][1] + pa.y;
                        sm->pre0[cj][r0 + 8]     = acc[mt][nt][2] + pb.x;
                        sm->pre0[cj + 1][r0 + 8] = acc[mt][nt][3] + pb.y;
                    }
                }
            }
        }
        __syncthreads();

        // ---- epilogue stage 2: warps 8-11 add U1 term into pre1 ----
        if (w >= 8) {
#pragma unroll
            for (int mt = 0; mt < 2; ++mt) {
                int r0 = wm + mt * 16 + g;
#pragma unroll
                for (int nt = 0; nt < 2; ++nt) {
                    int cj = wn + nt * 8 + q2;
                    sm->pre1[cj][r0]         += acc[mt][nt][0];
                    sm->pre1[cj + 1][r0]     += acc[mt][nt][1];
                    sm->pre1[cj][r0 + 8]     += acc[mt][nt][2];
                    sm->pre1[cj + 1][r0 + 8] += acc[mt][nt][3];
                }
            }
        }
        __syncthreads();

        // ---- cells (threads 0-255) ----
        if (tid < 256) {
#pragma unroll
            for (int half = 0; half < 2; ++half) {
                int b = cb + half * 32;
                {
                    float f  = sigf(sm->pre1[cu][b]);
                    float ii = sigf(sm->pre1[8 + cu][b]);
                    float gg = tanha(sm->pre1[16 + cu][b]);
                    float oo = sigf(sm->pre1[24 + cu][b]);
                    float cn = f * sm->c1[cu][b] + ii * gg;
                    sm->c1[cu][b] = cn;
                    float h = oo * tanha(cn);
                    h1w[b * HH + u0 + cu] = __float2half(h);
                    g_Hout[((size_t)b * SS + t) * HH + u0 + cu] = h;
                    if (t == SS - 1) {
                        out[98304 + 65536 + b * HH + u0 + cu] = h;
                        out[229376 + 65536 + b * HH + u0 + cu] = cn;
                    }
                }
                if (t < SS - 1) {
                    float f  = sigf(sm->pre0[cu][b]);
                    float ii = sigf(sm->pre0[8 + cu][b]);
                    float gg = tanha(sm->pre0[16 + cu][b]);
                    float oo = sigf(sm->pre0[24 + cu][b]);
                    float cn = f * sm->c0[cu][b] + ii * gg;
                    sm->c0[cu][b] = cn;
                    float h = oo * tanha(cn);
                    h0w[b * HH + u0 + cu] = __float2half(h);
                    if (t == SS - 2) {
                        out[98304 + b * HH + u0 + cu] = h;
                        out[229376 + b * HH + u0 + cu] = cn;
                    }
                }
            }
        }
        gbar(epoch);
    }
}

__global__ void __launch_bounds__(256)
head_kernel(const float* __restrict__ fcW, const float* __restrict__ fcb,
            float* __restrict__ out)
{
    int warp = (blockIdx.x * blockDim.x + threadIdx.x) >> 5;
    int lane = threadIdx.x & 31;
    if (warp >= BB * SS) return;
    const float* hrow = &g_Hout[(size_t)warp * HH];
    float a0 = 0.f, a1 = 0.f, a2 = 0.f;
    for (int k = lane; k < HH; k += 32) {
        float h = __ldg(&hrow[k]);
        a0 += h * __ldg(&fcW[k * 3 + 0]);
        a1 += h * __ldg(&fcW[k * 3 + 1]);
        a2 += h * __ldg(&fcW[k * 3 + 2]);
    }
#pragma unroll
    for (int off = 16; off; off >>= 1) {
        a0 += __shfl_xor_sync(0xffffffffu, a0, off);
        a1 += __shfl_xor_sync(0xffffffffu, a1, off);
        a2 += __shfl_xor_sync(0xffffffffu, a2, off);
    }
    if (lane == 0) {
        out[warp * 3 + 0] = a0 + __ldg(&fcb[0]);
        out[warp * 3 + 1] = a1 + __ldg(&fcb[1]);
        out[warp * 3 + 2] = a2 + __ldg(&fcb[2]);
    }
}

extern "C" void kernel_launch(void* const* d_in, const int* in_sizes, int n_in,
                              void* d_out, int out_size)
{
    const float* x    = (const float*)d_in[0];
    const float* z    = (const float*)d_in[1];
    const float* W0   = (const float*)d_in[2];
    const float* bW0  = (const float*)d_in[3];
    const float* U0   = (const float*)d_in[4];
    const float* V0   = (const float*)d_in[5];
    const float* b0   = (const float*)d_in[6];
    const float* W1   = (const float*)d_in[7];
    const float* bW1  = (const float*)d_in[8];
    const float* U1   = (const float*)d_in[9];
    const float* V1   = (const float*)d_in[10];
    const float* b1   = (const float*)d_in[11];
    const float* fcW  = (const float*)d_in[12];
    const float* fcb  = (const float*)d_in[13];
    float* out = (float*)d_out;

    static int smem_set = 0;
    if (!smem_set) {
        cudaFuncSetAttribute(recur_kernel, cudaFuncAttributeMaxDynamicSharedMemorySize,
                             REC_SMEM_BYTES);
        cudaFuncSetAttribute(gemm_mma_kernel, cudaFuncAttributeMaxDynamicSharedMemorySize,
                             G_SMEM_BYTES);
        smem_set = 1;
    }

    prep2a_kernel<<<2048, 256>>>(x, z);
    prep_all_kernel<<<dim3(64, 16, 6), 256>>>(U0, W1, U1, W0, V0, V1);
    gemm_mma_kernel<<<dim3(64, 512, 2), 256, G_SMEM_BYTES>>>(bW0, b0, bW1, b1);
    recur_kernel<<<NCTA, RTH, REC_SMEM_BYTES>>>(out);
    head_kernel<<<4096, 256>>>(fcW, fcb, out);
}

// round 13
// speedup vs baseline: 1.1066x; 1.1066x over previous
#include <cuda_runtime.h>
#include <cuda_fp16.h>
#include <math.h>

#define BB   64
#define SS   512
#define HH   1024
#define G4   4096
#define NCTA 128
#define KC   64
#define NCH  16
#define PK   72
#define PK2  1032
#define KA   640

typedef unsigned int u32;

__device__ float g_P0[BB * SS * G4];
__device__ float g_P1[BB * SS * G4];
__device__ float g_Hout[BB * SS * HH];
__device__ __half g_Wt[3ULL * G4 * HH];   // recur weights [mat][col][k]
__device__ __half g_A[BB * SS * KA];      // [r][640] = [x|z] fp16
__device__ __half g_B0[G4 * KA];          // [n][640] = [W0|V0]^T fp16
__device__ __half g_B1[G4 * 128];         // [n][128] = V1^T fp16
__device__ __half g_h0[2][BB * HH];
__device__ __half g_h1[2][BB * HH];
__device__ unsigned g_bar;

__device__ __forceinline__ float4 ldg4(const float* p)  { return __ldg((const float4*)p); }
__device__ __forceinline__ float sigf(float x)  { return 1.0f / (1.0f + __expf(-x)); }
__device__ __forceinline__ float tanha(float x) { return 1.0f - 2.0f / (__expf(2.0f * x) + 1.0f); }

__device__ __forceinline__ void mma_h(float* c, u32 a0, u32 a1, u32 a2, u32 a3,
                                      u32 b0, u32 b1)
{
    asm volatile(
        "mma.sync.aligned.m16n8k16.row.col.f32.f16.f16.f32 "
        "{%0,%1,%2,%3}, {%4,%5,%6,%7}, {%8,%9}, {%0,%1,%2,%3};\n"
        : "+f"(c[0]), "+f"(c[1]), "+f"(c[2]), "+f"(c[3])
        : "r"(a0), "r"(a1), "r"(a2), "r"(a3), "r"(b0), "r"(b1));
}
__device__ __forceinline__ void ldsm4(u32& r0, u32& r1, u32& r2, u32& r3, u32 a)
{
    asm volatile("ldmatrix.sync.aligned.m8n8.x4.shared.b16 {%0,%1,%2,%3}, [%4];\n"
                 : "=r"(r0), "=r"(r1), "=r"(r2), "=r"(r3) : "r"(a));
}
__device__ __forceinline__ void cpa16(void* dst, const void* src) {
    u32 d = (u32)__cvta_generic_to_shared(dst);
    asm volatile("cp.async.cg.shared.global [%0], [%1], 16;\n" :: "r"(d), "l"(src));
}
#define CP_COMMIT() asm volatile("cp.async.commit_group;\n" ::: "memory")

// ---------------- prep2a + init (merged) -------------------------------------
__global__ void __launch_bounds__(256)
prep2a_kernel(const float* __restrict__ x, const float* __restrict__ z)
{
    size_t gtid = (size_t)blockIdx.x * blockDim.x + threadIdx.x;
    size_t stride = (size_t)gridDim.x * blockDim.x;
    __half hz = __float2half(0.f);
    for (size_t i = gtid; i < BB * HH; i += stride) {
        g_h0[0][i] = hz; g_h0[1][i] = hz;
        g_h1[0][i] = hz; g_h1[1][i] = hz;
    }
    if (gtid == 0) g_bar = 0u;
    size_t total = (size_t)BB * SS * KA;
    for (size_t idx = gtid; idx < total; idx += stride) {
        size_t r = idx / KA;
        int k = (int)(idx - r * KA);
        float v = (k < 512) ? __ldg(&x[r * 512 + k]) : __ldg(&z[r * 128 + (k - 512)]);
        g_A[idx] = __float2half(v);
    }
}

// ---------------- prep_all (merged transpose kernels) ------------------------
__global__ void __launch_bounds__(256)
prep_all_kernel(const float* __restrict__ U0, const float* __restrict__ W1,
                const float* __restrict__ U1, const float* __restrict__ W0,
                const float* __restrict__ V0, const float* __restrict__ V1)
{
    int zi = blockIdx.z;
    __shared__ float tile[64][65];
    int tid = threadIdx.x;
    if (zi < 3) {
        const float* src = (zi == 0) ? U0 : ((zi == 1) ? W1 : U1);
        int c0 = blockIdx.x * 64;
        int k0 = blockIdx.y * 64;
#pragma unroll
        for (int i = 0; i < 4; ++i) {
            int lin = tid + i * 256;
            int kr = lin >> 4, cq = lin & 15;
            float4 v = ldg4(src + (size_t)(k0 + kr) * G4 + c0 + cq * 4);
            tile[kr][cq * 4 + 0] = v.x; tile[kr][cq * 4 + 1] = v.y;
            tile[kr][cq * 4 + 2] = v.z; tile[kr][cq * 4 + 3] = v.w;
        }
        __syncthreads();
#pragma unroll
        for (int i = 0; i < 2; ++i) {
            int lin = tid + i * 256;
            int cr = lin >> 3, seg = (lin & 7) * 8;
            __half tmp[8];
#pragma unroll
            for (int j = 0; j < 8; ++j) tmp[j] = __float2half(tile[seg + j][cr]);
            *(uint4*)(g_Wt + ((size_t)zi * G4 + c0 + cr) * HH + k0 + seg) = *(uint4*)tmp;
        }
        return;
    }
    int which = zi - 3;
    if (which == 0) { if (blockIdx.y >= 8) return; }
    else            { if (blockIdx.y >= 2) return; }
    const float* W = (which == 0) ? W0 : ((which == 1) ? V0 : V1);
    int n0 = blockIdx.x * 64;
    int k0 = blockIdx.y * 64;
#pragma unroll
    for (int i = 0; i < 4; ++i) {
        int lin = tid + i * 256;
        int kr = lin >> 4, nq = lin & 15;
        float4 v = ldg4(W + (size_t)(k0 + kr) * G4 + n0 + nq * 4);
        tile[kr][nq * 4 + 0] = v.x; tile[kr][nq * 4 + 1] = v.y;
        tile[kr][nq * 4 + 2] = v.z; tile[kr][nq * 4 + 3] = v.w;
    }
    __syncthreads();
    __half* dst; int ldb, kb;
    if (which == 0)      { dst = g_B0; ldb = KA;  kb = k0; }
    else if (which == 1) { dst = g_B0; ldb = KA;  kb = 512 + k0; }
    else                 { dst = g_B1; ldb = 128; kb = k0; }
#pragma unroll
    for (int i = 0; i < 2; ++i) {
        int lin = tid + i * 256;
        int nr = lin >> 3, seg = (lin & 7) * 8;
        __half th[8];
#pragma unroll
        for (int j = 0; j < 8; ++j) th[j] = __float2half(tile[seg + j][nr]);
        *(uint4*)(dst + (size_t)(n0 + nr) * ldb + kb + seg) = *(uint4*)th;
    }
}

// ---------------- precompute GEMM: fp16 single-term --------------------------
struct GSmem {
    __half A[3][64][PK];
    __half B[3][64][PK];
};
#define G_SMEM_BYTES ((int)sizeof(GSmem))

__global__ void __launch_bounds__(256, 2)
gemm_mma_kernel(const float* __restrict__ bsA1, const float* __restrict__ bsA2,
                const float* __restrict__ bsB1, const float* __restrict__ bsB2)
{
    const int which = blockIdx.z;
    const __half* __restrict__ A; const __half* __restrict__ B;
    const float* bs1; const float* bs2;
    int ldb, K; float* OUT;
    if (which == 0) { A = g_A;       B = g_B0; ldb = KA;  K = KA;  OUT = g_P0; bs1 = bsA1; bs2 = bsA2; }
    else            { A = g_A + 512; B = g_B1; ldb = 128; K = 128; OUT = g_P1; bs1 = bsB1; bs2 = bsB2; }
    const int lda = KA;

    extern __shared__ unsigned char smraw[];
    GSmem* sm = (GSmem*)smraw;
    const int tid = threadIdx.x;
    const int n0 = blockIdx.x * 64;
    const int m0 = blockIdx.y * 64;
    const int lane = tid & 31, w = tid >> 5;
    const int g = lane >> 2, q2 = (lane & 3) * 2;
    const int lg = lane >> 3, lr = lane & 7;
    const int wm = (w >> 2) * 32;
    const int wn = (w & 3) * 16;
    const int nch = K / KC;

    const int l0 = tid * 2, l1 = tid * 2 + 1;
    const int ar0 = l0 >> 3, as0 = (l0 & 7) * 8;
    const int ar1 = l1 >> 3, as1 = (l1 & 7) * 8;

    const u32 bufstr = 64 * PK * 2;
    const u32 baseA = (u32)__cvta_generic_to_shared(&sm->A[0][0][0]);
    const u32 baseB = (u32)__cvta_generic_to_shared(&sm->B[0][0][0]);
    const u32 offA0 = (u32)(wm + (lg & 1) * 8 + lr) * (PK * 2) + (lg >> 1) * 16;
    const u32 offA1 = offA0 + 16 * (PK * 2);
    const u32 offB  = (u32)(wn + (lg >> 1) * 8 + lr) * (PK * 2) + (lg & 1) * 16;

    float acc[2][2][4];
#pragma unroll
    for (int a = 0; a < 2; ++a)
#pragma unroll
        for (int b = 0; b < 2; ++b)
#pragma unroll
            for (int c = 0; c < 4; ++c) acc[a][b][c] = 0.f;

#pragma unroll
    for (int pc = 0; pc < 2; ++pc) {
        int k0 = pc * KC;
        cpa16(&sm->A[pc][ar0][as0], A + (size_t)(m0 + ar0) * lda + k0 + as0);
        cpa16(&sm->A[pc][ar1][as1], A + (size_t)(m0 + ar1) * lda + k0 + as1);
        cpa16(&sm->B[pc][ar0][as0], B + (size_t)(n0 + ar0) * ldb + k0 + as0);
        cpa16(&sm->B[pc][ar1][as1], B + (size_t)(n0 + ar1) * ldb + k0 + as1);
        CP_COMMIT();
    }

    for (int ch = 0; ch < nch; ++ch) {
        if (ch < nch - 1) asm volatile("cp.async.wait_group 1;\n" ::: "memory");
        else              asm volatile("cp.async.wait_group 0;\n" ::: "memory");
        __syncthreads();
        if (ch + 2 < nch) {
            int buf = (ch + 2) % 3;
            int k0 = (ch + 2) * KC;
            cpa16(&sm->A[buf][ar0][as0], A + (size_t)(m0 + ar0) * lda + k0 + as0);
            cpa16(&sm->A[buf][ar1][as1], A + (size_t)(m0 + ar1) * lda + k0 + as1);
            cpa16(&sm->B[buf][ar0][as0], B + (size_t)(n0 + ar0) * ldb + k0 + as0);
            cpa16(&sm->B[buf][ar1][as1], B + (size_t)(n0 + ar1) * ldb + k0 + as1);
            CP_COMMIT();
        }
        const int buf = ch % 3;
        const u32 bo = buf * bufstr;
#pragma unroll
        for (int kk = 0; kk < 4; ++kk) {
            const u32 kb2 = kk * 32;
            u32 a[2][4], b[4];
            ldsm4(a[0][0], a[0][1], a[0][2], a[0][3], baseA + bo + offA0 + kb2);
            ldsm4(a[1][0], a[1][1], a[1][2], a[1][3], baseA + bo + offA1 + kb2);
            ldsm4(b[0], b[1], b[2], b[3], baseB + bo + offB + kb2);
#pragma unroll
            for (int nt = 0; nt < 2; ++nt)
#pragma unroll
                for (int mt = 0; mt < 2; ++mt)
                    mma_h(acc[mt][nt], a[mt][0], a[mt][1], a[mt][2], a[mt][3],
                          b[nt * 2], b[nt * 2 + 1]);
        }
    }

#pragma unroll
    for (int mt = 0; mt < 2; ++mt) {
        int r0 = m0 + wm + mt * 16 + g;
#pragma unroll
        for (int nt = 0; nt < 2; ++nt) {
            int c = n0 + wn + nt * 8 + q2;
            float b0 = __ldg(&bs1[c]) + __ldg(&bs2[c]);
            float b1 = __ldg(&bs1[c + 1]) + __ldg(&bs2[c + 1]);
            OUT[(size_t)r0 * G4 + c]           = acc[mt][nt][0] + b0;
            OUT[(size_t)r0 * G4 + c + 1]       = acc[mt][nt][1] + b1;
            OUT[(size_t)(r0 + 8) * G4 + c]     = acc[mt][nt][2] + b0;
            OUT[(size_t)(r0 + 8) * G4 + c + 1] = acc[mt][nt][3] + b1;
        }
    }
}

__device__ __forceinline__ void gbar(unsigned& epoch)
{
    __syncthreads();
    epoch += NCTA;
    if (threadIdx.x == 0) {
        __threadfence();
        atomicAdd(&g_bar, 1u);
        while (*(volatile unsigned*)&g_bar < epoch) { }
        __threadfence();
    }
    __syncthreads();
}

// ---------------- recurrent: 4-deep pipeline, U1 resident, P prefetched ------
struct RecSmem {
    __half A1[4][64][PK];
    __half A2[4][64][PK];
    __half B1[4][64][PK];     // streamed [W1 | U0] slice
    __half B2r[32][PK2];      // resident U1 slice
    float pre1[32][66];
    float pre0[32][66];
    float c0[8][66];
    float c1[8][66];
};
#define REC_SMEM_BYTES ((int)sizeof(RecSmem))

__global__ void __launch_bounds__(256, 1)
recur_kernel(float* __restrict__ out)
{
    extern __shared__ unsigned char smraw[];
    RecSmem* sm = (RecSmem*)smraw;

    const int tid = threadIdx.x;
    const int u0 = blockIdx.x * 8;
    const int lane = tid & 31, w = tid >> 5;
    const int g = lane >> 2, q2 = (lane & 3) * 2;
    const int lg = lane >> 3, lr = lane & 7;
    const int cu = tid & 7, cb = tid >> 3;

    const int lin1 = tid + 256;
    const int arow0 = tid >> 3,  aseg0 = (tid & 7) * 8;
    const int arow1 = lin1 >> 3, aseg1 = (lin1 & 7) * 8;
    const size_t offGA0 = (size_t)arow0 * HH + aseg0;
    const size_t offGA1 = (size_t)arow1 * HH + aseg1;
    const int jj0 = arow0 & 31, jj1 = arow1 & 31;
    const __half* pB1_0 = g_Wt + ((size_t)1 * G4 + ((jj0 >> 3) << 10) + u0 + (jj0 & 7)) * HH + aseg0;
    const __half* pB1_1 = g_Wt + ((size_t)0 * G4 + ((jj1 >> 3) << 10) + u0 + (jj1 & 7)) * HH + aseg1;

    const int wlo = (w < 4) ? w : (w - 4);
    const int wm = (wlo >> 1) * 32;
    const int wn = (w < 4) ? ((wlo & 1) * 32) : ((wlo & 1) * 16);

    const u32 bufstr = 64 * PK * 2;
    const u32 baseA1 = (u32)__cvta_generic_to_shared(&sm->A1[0][0][0]);
    const u32 baseA2 = (u32)__cvta_generic_to_shared(&sm->A2[0][0][0]);
    const u32 baseB1 = (u32)__cvta_generic_to_shared(&sm->B1[0][0][0]);
    const u32 baseB2 = (u32)__cvta_generic_to_shared(&sm->B2r[0][0]);
    const u32 offA_0 = (u32)(wm + (lg & 1) * 8 + lr) * (PK * 2) + (lg >> 1) * 16;
    const u32 offA_1 = offA_0 + 16 * (PK * 2);
    const u32 offB1_0 = (u32)(wn + (lg >> 1) * 8 + lr) * (PK * 2) + (lg & 1) * 16;
    const u32 offB1_1 = offB1_0 + 16 * (PK * 2);
    const u32 offB2  = (u32)(wn + (lg >> 1) * 8 + lr) * (PK2 * 2) + (lg & 1) * 16;

    // resident U1 slice
#pragma unroll
    for (int i = 0; i < 16; ++i) {
        int lin = tid + i * 256;
        int row = lin >> 7, seg = (lin & 127) * 8;
        size_t c = ((size_t)2 * G4 + ((row >> 3) << 10) + u0 + (row & 7));
        *(uint4*)&sm->B2r[row][seg] = *(const uint4*)(g_Wt + c * HH + seg);
    }
    for (int i = tid; i < 8 * 66; i += 256) {
        ((float*)sm->c0)[i] = 0.f;
        ((float*)sm->c1)[i] = 0.f;
    }
    __syncthreads();
#pragma unroll
    for (int half = 0; half < 2; ++half) {
        int b = cb + half * 32;
        size_t base = ((size_t)b * SS) * G4 + u0 + cu;
        float pi = g_P0[base + 1024];
        float pg = g_P0[base + 2048];
        float po = g_P0[base + 3072];
        float cn = sigf(pi) * tanha(pg);
        sm->c0[cu][b] = cn;
        g_h0[0][b * HH + u0 + cu] = __float2half(sigf(po) * tanha(cn));
    }
    unsigned epoch = 0;
    gbar(epoch);

    for (int t = 0; t < SS; ++t) {
        const __half* h0r = g_h0[t & 1];
        const __half* h1r = g_h1[(t + 1) & 1];
        __half* h0w = g_h0[(t + 1) & 1];
        __half* h1w = g_h1[t & 1];

        // ---- P prefetch into registers (overlapped with the whole GEMM) ----
        float2 pP[2][4][2];
        const bool isL1p = (w < 4) && (wn == 0);
        const bool isL0p = (w < 4) && (wn != 0) && (t < SS - 1);
        if (isL1p || isL0p) {
            const float* Pb = isL1p ? g_P1 : g_P0;
            const int tt = isL1p ? t : t + 1;
#pragma unroll
            for (int mt = 0; mt < 2; ++mt) {
                int r0 = wm + mt * 16 + g;
#pragma unroll
                for (int nt = 0; nt < 4; ++nt) {
                    int cj = nt * 8 + q2;
                    int gate = cj >> 3, un = cj & 7;
                    const float* base = Pb + ((size_t)gate << 10) + u0 + un;
                    pP[mt][nt][0] = *(const float2*)(base + ((size_t)r0 * SS + tt) * G4);
                    pP[mt][nt][1] = *(const float2*)(base + ((size_t)(r0 + 8) * SS + tt) * G4);
                }
            }
        }

        float acc[2][4][4];
#pragma unroll
        for (int a = 0; a < 2; ++a)
#pragma unroll
            for (int b = 0; b < 4; ++b)
#pragma unroll
                for (int c = 0; c < 4; ++c) acc[a][b][c] = 0.f;

#pragma unroll
        for (int pc = 0; pc < 3; ++pc) {
            int k0 = pc * KC;
            cpa16(&sm->A1[pc][arow0][aseg0], h0r + offGA0 + k0);
            cpa16(&sm->A1[pc][arow1][aseg1], h0r + offGA1 + k0);
            cpa16(&sm->A2[pc][arow0][aseg0], h1r + offGA0 + k0);
            cpa16(&sm->A2[pc][arow1][aseg1], h1r + offGA1 + k0);
            cpa16(&sm->B1[pc][arow0][aseg0], pB1_0 + k0);
            cpa16(&sm->B1[pc][arow1][aseg1], pB1_1 + k0);
            CP_COMMIT();
        }

        for (int ch = 0; ch < NCH; ++ch) {
            if (ch <= NCH - 3)      asm volatile("cp.async.wait_group 2;\n" ::: "memory");
            else if (ch == NCH - 2) asm volatile("cp.async.wait_group 1;\n" ::: "memory");
            else                    asm volatile("cp.async.wait_group 0;\n" ::: "memory");
            __syncthreads();
            if (ch + 3 < NCH) {
                int buf = (ch + 3) & 3;
                int k0 = (ch + 3) * KC;
                cpa16(&sm->A1[buf][arow0][aseg0], h0r + offGA0 + k0);
                cpa16(&sm->A1[buf][arow1][aseg1], h0r + offGA1 + k0);
                cpa16(&sm->A2[buf][arow0][aseg0], h1r + offGA0 + k0);
                cpa16(&sm->A2[buf][arow1][aseg1], h1r + offGA1 + k0);
                cpa16(&sm->B1[buf][arow0][aseg0], pB1_0 + k0);
                cpa16(&sm->B1[buf][arow1][aseg1], pB1_1 + k0);
                CP_COMMIT();
            }
            const int buf = ch & 3;
            const u32 bo = buf * bufstr;
            if (w < 4) {
#pragma unroll
                for (int kk = 0; kk < 4; ++kk) {
                    const u32 kb2 = kk * 32;
                    u32 a[2][4], bA[4], bB[4];
                    ldsm4(a[0][0], a[0][1], a[0][2], a[0][3], baseA1 + bo + offA_0 + kb2);
                    ldsm4(a[1][0], a[1][1], a[1][2], a[1][3], baseA1 + bo + offA_1 + kb2);
                    ldsm4(bA[0], bA[1], bA[2], bA[3], baseB1 + bo + offB1_0 + kb2);
                    ldsm4(bB[0], bB[1], bB[2], bB[3], baseB1 + bo + offB1_1 + kb2);
#pragma unroll
                    for (int nt = 0; nt < 4; ++nt) {
                        u32 b0 = (nt < 2) ? bA[(nt & 1) * 2]     : bB[(nt & 1) * 2];
                        u32 b1 = (nt < 2) ? bA[(nt & 1) * 2 + 1] : bB[(nt & 1) * 2 + 1];
                        mma_h(acc[0][nt], a[0][0], a[0][1], a[0][2], a[0][3], b0, b1);
                        mma_h(acc[1][nt], a[1][0], a[1][1], a[1][2], a[1][3], b0, b1);
                    }
                }
            } else {
                const u32 kgl2 = (u32)(ch * KC) * 2;
#pragma unroll
                for (int kk = 0; kk < 4; ++kk) {
                    const u32 kb2 = kk * 32;
                    u32 a[2][4], bA[4];
                    ldsm4(a[0][0], a[0][1], a[0][2], a[0][3], baseA2 + bo + offA_0 + kb2);
                    ldsm4(a[1][0], a[1][1], a[1][2], a[1][3], baseA2 + bo + offA_1 + kb2);
                    ldsm4(bA[0], bA[1], bA[2], bA[3], baseB2 + offB2 + kgl2 + kb2);
#pragma unroll
                    for (int nt = 0; nt < 2; ++nt) {
                        u32 b0 = bA[nt * 2], b1 = bA[nt * 2 + 1];
                        mma_h(acc[0][nt], a[0][0], a[0][1], a[0][2], a[0][3], b0, b1);
                        mma_h(acc[1][nt], a[1][0], a[1][1], a[1][2], a[1][3], b0, b1);
                    }
                }
            }
        }
        __syncthreads();

        // ---- epilogue stage 1: warps 0-3 write pre1/pre0 (+P from regs) ----
        if (w < 4) {
            const bool isL1 = (wn == 0);
#pragma unroll
            for (int mt = 0; mt < 2; ++mt) {
                int r0 = wm + mt * 16 + g;
#pragma unroll
                for (int nt = 0; nt < 4; ++nt) {
                    int cj = nt * 8 + q2;
                    if (isL1) {
                        sm->pre1[cj][r0]         = acc[mt][nt][0] + pP[mt][nt][0].x;
                        sm->pre1[cj + 1][r0]     = acc[mt][nt][1] + pP[mt][nt][0].y;
                        sm->pre1[cj][r0 + 8]     = acc[mt][nt][2] + pP[mt][nt][1].x;
                        sm->pre1[cj + 1][r0 + 8] = acc[mt][nt][3] + pP[mt][nt][1].y;
                    } else if (t < SS - 1) {
                        sm->pre0[cj][r0]         = acc[mt][nt][0] + pP[mt][nt][0].x;
                        sm->pre0[cj + 1][r0]     = acc[mt][nt][1] + pP[mt][nt][0].y;
                        sm->pre0[cj][r0 + 8]     = acc[mt][nt][2] + pP[mt][nt][1].x;
                        sm->pre0[cj + 1][r0 + 8] = acc[mt][nt][3] + pP[mt][nt][1].y;
                    }
                }
            }
        }
        __syncthreads();

        // ---- epilogue stage 2: warps 4-7 add U1 term into pre1 ----
        if (w >= 4) {
#pragma unroll
            for (int mt = 0; mt < 2; ++mt) {
                int r0 = wm + mt * 16 + g;
#pragma unroll
                for (int nt = 0; nt < 2; ++nt) {
                    int cj = wn + nt * 8 + q2;
                    sm->pre1[cj][r0]         += acc[mt][nt][0];
                    sm->pre1[cj + 1][r0]     += acc[mt][nt][1];
                    sm->pre1[cj][r0 + 8]     += acc[mt][nt][2];
                    sm->pre1[cj + 1][r0 + 8] += acc[mt][nt][3];
                }
            }
        }
        __syncthreads();

        // ---- cells ----
#pragma unroll
        for (int half = 0; half < 2; ++half) {
            int b = cb + half * 32;
            {
                float f  = sigf(sm->pre1[cu][b]);
                float ii = sigf(sm->pre1[8 + cu][b]);
                float gg = tanha(sm->pre1[16 + cu][b]);
                float oo = sigf(sm->pre1[24 + cu][b]);
                float cn = f * sm->c1[cu][b] + ii * gg;
                sm->c1[cu][b] = cn;
                float h = oo * tanha(cn);
                h1w[b * HH + u0 + cu] = __float2half(h);
                g_Hout[((size_t)b * SS + t) * HH + u0 + cu] = h;
                if (t == SS - 1) {
                    out[98304 + 65536 + b * HH + u0 + cu] = h;
                    out[229376 + 65536 + b * HH + u0 + cu] = cn;
                }
            }
            if (t < SS - 1) {
                float f  = sigf(sm->pre0[cu][b]);
                float ii = sigf(sm->pre0[8 + cu][b]);
                float gg = tanha(sm->pre0[16 + cu][b]);
                float oo = sigf(sm->pre0[24 + cu][b]);
                float cn = f * sm->c0[cu][b] + ii * gg;
                sm->c0[cu][b] = cn;
                float h = oo * tanha(cn);
                h0w[b * HH + u0 + cu] = __float2half(h);
                if (t == SS - 2) {
                    out[98304 + b * HH + u0 + cu] = h;
                    out[229376 + b * HH + u0 + cu] = cn;
                }
            }
        }
        gbar(epoch);
    }
}

__global__ void __launch_bounds__(256)
head_kernel(const float* __restrict__ fcW, const float* __restrict__ fcb,
            float* __restrict__ out)
{
    int warp = (blockIdx.x * blockDim.x + threadIdx.x) >> 5;
    int lane = threadIdx.x & 31;
    if (warp >= BB * SS) return;
    const float* hrow = &g_Hout[(size_t)warp * HH];
    float a0 = 0.f, a1 = 0.f, a2 = 0.f;
    for (int k = lane; k < HH; k += 32) {
        float h = __ldg(&hrow[k]);
        a0 += h * __ldg(&fcW[k * 3 + 0]);
        a1 += h * __ldg(&fcW[k * 3 + 1]);
        a2 += h * __ldg(&fcW[k * 3 + 2]);
    }
#pragma unroll
    for (int off = 16; off; off >>= 1) {
        a0 += __shfl_xor_sync(0xffffffffu, a0, off);
        a1 += __shfl_xor_sync(0xffffffffu, a1, off);
        a2 += __shfl_xor_sync(0xffffffffu, a2, off);
    }
    if (lane == 0) {
        out[warp * 3 + 0] = a0 + __ldg(&fcb[0]);
        out[warp * 3 + 1] = a1 + __ldg(&fcb[1]);
        out[warp * 3 + 2] = a2 + __ldg(&fcb[2]);
    }
}

extern "C" void kernel_launch(void* const* d_in, const int* in_sizes, int n_in,
                              void* d_out, int out_size)
{
    const float* x    = (const float*)d_in[0];
    const float* z    = (const float*)d_in[1];
    const float* W0   = (const float*)d_in[2];
    const float* bW0  = (const float*)d_in[3];
    const float* U0   = (const float*)d_in[4];
    const float* V0   = (const float*)d_in[5];
    const float* b0   = (const float*)d_in[6];
    const float* W1   = (const float*)d_in[7];
    const float* bW1  = (const float*)d_in[8];
    const float* U1   = (const float*)d_in[9];
    const float* V1   = (const float*)d_in[10];
    const float* b1   = (const float*)d_in[11];
    const float* fcW  = (const float*)d_in[12];
    const float* fcb  = (const float*)d_in[13];
    float* out = (float*)d_out;

    static int smem_set = 0;
    if (!smem_set) {
        cudaFuncSetAttribute(recur_kernel, cudaFuncAttributeMaxDynamicSharedMemorySize,
                             REC_SMEM_BYTES);
        cudaFuncSetAttribute(gemm_mma_kernel, cudaFuncAttributeMaxDynamicSharedMemorySize,
                             G_SMEM_BYTES);
        smem_set = 1;
    }

    prep2a_kernel<<<2048, 256>>>(x, z);
    prep_all_kernel<<<dim3(64, 16, 6), 256>>>(U0, W1, U1, W0, V0, V1);
    gemm_mma_kernel<<<dim3(64, 512, 2), 256, G_SMEM_BYTES>>>(bW0, b0, bW1, b1);
    recur_kernel<<<NCTA, 256, REC_SMEM_BYTES>>>(out);
    head_kernel<<<4096, 256>>>(fcW, fcb, out);
}

// round 14
// speedup vs baseline: 1.1391x; 1.0294x over previous
#include <cuda_runtime.h>
#include <cuda_fp16.h>
#include <math.h>

#define BB   64
#define SS   512
#define HH   1024
#define G4   4096
#define NCTA 128
#define KC   64
#define PK   72
#define PK2  1032
#define KA   640
#define RKC  128
#define RNCH 8
#define RPK  136

typedef unsigned int u32;

__device__ float g_P0[BB * SS * G4];
__device__ float g_P1[BB * SS * G4];
__device__ float g_Hout[BB * SS * HH];
__device__ __half g_Wt[3ULL * G4 * HH];   // recur weights [mat][col][k]
__device__ __half g_A[BB * SS * KA];      // [r][640] = [x|z] fp16
__device__ __half g_B0[G4 * KA];          // [n][640] = [W0|V0]^T fp16
__device__ __half g_B1[G4 * 128];         // [n][128] = V1^T fp16
__device__ __half g_h0[2][BB * HH];
__device__ __half g_h1[2][BB * HH];
__device__ unsigned g_bar;

__device__ __forceinline__ float4 ldg4(const float* p)  { return __ldg((const float4*)p); }
__device__ __forceinline__ float sigf(float x)  { return 1.0f / (1.0f + __expf(-x)); }
__device__ __forceinline__ float tanha(float x) { return 1.0f - 2.0f / (__expf(2.0f * x) + 1.0f); }

__device__ __forceinline__ void mma_h(float* c, u32 a0, u32 a1, u32 a2, u32 a3,
                                      u32 b0, u32 b1)
{
    asm volatile(
        "mma.sync.aligned.m16n8k16.row.col.f32.f16.f16.f32 "
        "{%0,%1,%2,%3}, {%4,%5,%6,%7}, {%8,%9}, {%0,%1,%2,%3};\n"
        : "+f"(c[0]), "+f"(c[1]), "+f"(c[2]), "+f"(c[3])
        : "r"(a0), "r"(a1), "r"(a2), "r"(a3), "r"(b0), "r"(b1));
}
__device__ __forceinline__ void ldsm4(u32& r0, u32& r1, u32& r2, u32& r3, u32 a)
{
    asm volatile("ldmatrix.sync.aligned.m8n8.x4.shared.b16 {%0,%1,%2,%3}, [%4];\n"
                 : "=r"(r0), "=r"(r1), "=r"(r2), "=r"(r3) : "r"(a));
}
__device__ __forceinline__ void cpa16(void* dst, const void* src) {
    u32 d = (u32)__cvta_generic_to_shared(dst);
    asm volatile("cp.async.cg.shared.global [%0], [%1], 16;\n" :: "r"(d), "l"(src));
}
__device__ __forceinline__ void cpa16u(u32 dst, const void* src) {
    asm volatile("cp.async.cg.shared.global [%0], [%1], 16;\n" :: "r"(dst), "l"(src));
}
#define CP_COMMIT() asm volatile("cp.async.commit_group;\n" ::: "memory")

// ---------------- prep2a + init (merged) -------------------------------------
__global__ void __launch_bounds__(256)
prep2a_kernel(const float* __restrict__ x, const float* __restrict__ z)
{
    size_t gtid = (size_t)blockIdx.x * blockDim.x + threadIdx.x;
    size_t stride = (size_t)gridDim.x * blockDim.x;
    __half hz = __float2half(0.f);
    for (size_t i = gtid; i < BB * HH; i += stride) {
        g_h0[0][i] = hz; g_h0[1][i] = hz;
        g_h1[0][i] = hz; g_h1[1][i] = hz;
    }
    if (gtid == 0) g_bar = 0u;
    size_t total = (size_t)BB * SS * KA;
    for (size_t idx = gtid; idx < total; idx += stride) {
        size_t r = idx / KA;
        int k = (int)(idx - r * KA);
        float v = (k < 512) ? __ldg(&x[r * 512 + k]) : __ldg(&z[r * 128 + (k - 512)]);
        g_A[idx] = __float2half(v);
    }
}

// ---------------- prep_all (merged transpose kernels) ------------------------
__global__ void __launch_bounds__(256)
prep_all_kernel(const float* __restrict__ U0, const float* __restrict__ W1,
                const float* __restrict__ U1, const float* __restrict__ W0,
                const float* __restrict__ V0, const float* __restrict__ V1)
{
    int zi = blockIdx.z;
    __shared__ float tile[64][65];
    int tid = threadIdx.x;
    if (zi < 3) {
        const float* src = (zi == 0) ? U0 : ((zi == 1) ? W1 : U1);
        int c0 = blockIdx.x * 64;
        int k0 = blockIdx.y * 64;
#pragma unroll
        for (int i = 0; i < 4; ++i) {
            int lin = tid + i * 256;
            int kr = lin >> 4, cq = lin & 15;
            float4 v = ldg4(src + (size_t)(k0 + kr) * G4 + c0 + cq * 4);
            tile[kr][cq * 4 + 0] = v.x; tile[kr][cq * 4 + 1] = v.y;
            tile[kr][cq * 4 + 2] = v.z; tile[kr][cq * 4 + 3] = v.w;
        }
        __syncthreads();
#pragma unroll
        for (int i = 0; i < 2; ++i) {
            int lin = tid + i * 256;
            int cr = lin >> 3, seg = (lin & 7) * 8;
            __half tmp[8];
#pragma unroll
            for (int j = 0; j < 8; ++j) tmp[j] = __float2half(tile[seg + j][cr]);
            *(uint4*)(g_Wt + ((size_t)zi * G4 + c0 + cr) * HH + k0 + seg) = *(uint4*)tmp;
        }
        return;
    }
    int which = zi - 3;
    if (which == 0) { if (blockIdx.y >= 8) return; }
    else            { if (blockIdx.y >= 2) return; }
    const float* W = (which == 0) ? W0 : ((which == 1) ? V0 : V1);
    int n0 = blockIdx.x * 64;
    int k0 = blockIdx.y * 64;
#pragma unroll
    for (int i = 0; i < 4; ++i) {
        int lin = tid + i * 256;
        int kr = lin >> 4, nq = lin & 15;
        float4 v = ldg4(W + (size_t)(k0 + kr) * G4 + n0 + nq * 4);
        tile[kr][nq * 4 + 0] = v.x; tile[kr][nq * 4 + 1] = v.y;
        tile[kr][nq * 4 + 2] = v.z; tile[kr][nq * 4 + 3] = v.w;
    }
    __syncthreads();
    __half* dst; int ldb, kb;
    if (which == 0)      { dst = g_B0; ldb = KA;  kb = k0; }
    else if (which == 1) { dst = g_B0; ldb = KA;  kb = 512 + k0; }
    else                 { dst = g_B1; ldb = 128; kb = k0; }
#pragma unroll
    for (int i = 0; i < 2; ++i) {
        int lin = tid + i * 256;
        int nr = lin >> 3, seg = (lin & 7) * 8;
        __half th[8];
#pragma unroll
        for (int j = 0; j < 8; ++j) th[j] = __float2half(tile[seg + j][nr]);
        *(uint4*)(dst + (size_t)(n0 + nr) * ldb + kb + seg) = *(uint4*)th;
    }
}

// ---------------- precompute GEMM: fp16 single-term --------------------------
struct GSmem {
    __half A[3][64][PK];
    __half B[3][64][PK];
};
#define G_SMEM_BYTES ((int)sizeof(GSmem))

__global__ void __launch_bounds__(256, 2)
gemm_mma_kernel(const float* __restrict__ bsA1, const float* __restrict__ bsA2,
                const float* __restrict__ bsB1, const float* __restrict__ bsB2)
{
    const int which = blockIdx.z;
    const __half* __restrict__ A; const __half* __restrict__ B;
    const float* bs1; const float* bs2;
    int ldb, K; float* OUT;
    if (which == 0) { A = g_A;       B = g_B0; ldb = KA;  K = KA;  OUT = g_P0; bs1 = bsA1; bs2 = bsA2; }
    else            { A = g_A + 512; B = g_B1; ldb = 128; K = 128; OUT = g_P1; bs1 = bsB1; bs2 = bsB2; }
    const int lda = KA;

    extern __shared__ unsigned char smraw[];
    GSmem* sm = (GSmem*)smraw;
    const int tid = threadIdx.x;
    const int n0 = blockIdx.x * 64;
    const int m0 = blockIdx.y * 64;
    const int lane = tid & 31, w = tid >> 5;
    const int g = lane >> 2, q2 = (lane & 3) * 2;
    const int lg = lane >> 3, lr = lane & 7;
    const int wm = (w >> 2) * 32;
    const int wn = (w & 3) * 16;
    const int nch = K / KC;

    const int l0 = tid * 2, l1 = tid * 2 + 1;
    const int ar0 = l0 >> 3, as0 = (l0 & 7) * 8;
    const int ar1 = l1 >> 3, as1 = (l1 & 7) * 8;

    const u32 bufstr = 64 * PK * 2;
    const u32 baseA = (u32)__cvta_generic_to_shared(&sm->A[0][0][0]);
    const u32 baseB = (u32)__cvta_generic_to_shared(&sm->B[0][0][0]);
    const u32 offA0 = (u32)(wm + (lg & 1) * 8 + lr) * (PK * 2) + (lg >> 1) * 16;
    const u32 offA1 = offA0 + 16 * (PK * 2);
    const u32 offB  = (u32)(wn + (lg >> 1) * 8 + lr) * (PK * 2) + (lg & 1) * 16;

    float acc[2][2][4];
#pragma unroll
    for (int a = 0; a < 2; ++a)
#pragma unroll
        for (int b = 0; b < 2; ++b)
#pragma unroll
            for (int c = 0; c < 4; ++c) acc[a][b][c] = 0.f;

#pragma unroll
    for (int pc = 0; pc < 2; ++pc) {
        int k0 = pc * KC;
        cpa16(&sm->A[pc][ar0][as0], A + (size_t)(m0 + ar0) * lda + k0 + as0);
        cpa16(&sm->A[pc][ar1][as1], A + (size_t)(m0 + ar1) * lda + k0 + as1);
        cpa16(&sm->B[pc][ar0][as0], B + (size_t)(n0 + ar0) * ldb + k0 + as0);
        cpa16(&sm->B[pc][ar1][as1], B + (size_t)(n0 + ar1) * ldb + k0 + as1);
        CP_COMMIT();
    }

    for (int ch = 0; ch < nch; ++ch) {
        if (ch < nch - 1) asm volatile("cp.async.wait_group 1;\n" ::: "memory");
        else              asm volatile("cp.async.wait_group 0;\n" ::: "memory");
        __syncthreads();
        if (ch + 2 < nch) {
            int buf = (ch + 2) % 3;
            int k0 = (ch + 2) * KC;
            cpa16(&sm->A[buf][ar0][as0], A + (size_t)(m0 + ar0) * lda + k0 + as0);
            cpa16(&sm->A[buf][ar1][as1], A + (size_t)(m0 + ar1) * lda + k0 + as1);
            cpa16(&sm->B[buf][ar0][as0], B + (size_t)(n0 + ar0) * ldb + k0 + as0);
            cpa16(&sm->B[buf][ar1][as1], B + (size_t)(n0 + ar1) * ldb + k0 + as1);
            CP_COMMIT();
        }
        const int buf = ch % 3;
        const u32 bo = buf * bufstr;
#pragma unroll
        for (int kk = 0; kk < 4; ++kk) {
            const u32 kb2 = kk * 32;
            u32 a[2][4], b[4];
            ldsm4(a[0][0], a[0][1], a[0][2], a[0][3], baseA + bo + offA0 + kb2);
            ldsm4(a[1][0], a[1][1], a[1][2], a[1][3], baseA + bo + offA1 + kb2);
            ldsm4(b[0], b[1], b[2], b[3], baseB + bo + offB + kb2);
#pragma unroll
            for (int nt = 0; nt < 2; ++nt)
#pragma unroll
                for (int mt = 0; mt < 2; ++mt)
                    mma_h(acc[mt][nt], a[mt][0], a[mt][1], a[mt][2], a[mt][3],
                          b[nt * 2], b[nt * 2 + 1]);
        }
    }

#pragma unroll
    for (int mt = 0; mt < 2; ++mt) {
        int r0 = m0 + wm + mt * 16 + g;
#pragma unroll
        for (int nt = 0; nt < 2; ++nt) {
            int c = n0 + wn + nt * 8 + q2;
            float b0 = __ldg(&bs1[c]) + __ldg(&bs2[c]);
            float b1 = __ldg(&bs1[c + 1]) + __ldg(&bs2[c + 1]);
            OUT[(size_t)r0 * G4 + c]           = acc[mt][nt][0] + b0;
            OUT[(size_t)r0 * G4 + c + 1]       = acc[mt][nt][1] + b1;
            OUT[(size_t)(r0 + 8) * G4 + c]     = acc[mt][nt][2] + b0;
            OUT[(size_t)(r0 + 8) * G4 + c + 1] = acc[mt][nt][3] + b1;
        }
    }
}

__device__ __forceinline__ void gbar(unsigned& epoch)
{
    __syncthreads();
    epoch += NCTA;
    if (threadIdx.x == 0) {
        __threadfence();
        atomicAdd(&g_bar, 1u);
        while (*(volatile unsigned*)&g_bar < epoch) { }
        __threadfence();
    }
    __syncthreads();
}

// ---------------- recurrent: KC=128, 8 chunks, disjoint epilogue buffers -----
struct RecSmem {
    __half A1[2][64][RPK];
    __half A2[2][64][RPK];
    __half B1[2][64][RPK];    // streamed [W1 | U0] slice
    __half B2r[32][PK2];      // resident U1 slice
    float pre1[32][66];
    float pre1b[32][66];
    float pre0[32][66];
    float c0[8][66];
    float c1[8][66];
};
#define REC_SMEM_BYTES ((int)sizeof(RecSmem))

__global__ void __launch_bounds__(256, 1)
recur_kernel(float* __restrict__ out)
{
    extern __shared__ unsigned char smraw[];
    RecSmem* sm = (RecSmem*)smraw;

    const int tid = threadIdx.x;
    const int u0 = blockIdx.x * 8;
    const int lane = tid & 31, w = tid >> 5;
    const int g = lane >> 2, q2 = (lane & 3) * 2;
    const int lg = lane >> 3, lr = lane & 7;
    const int cu = tid & 7, cb = tid >> 3;

    // staging: 4 (row,seg) pairs shared by A1/A2/B1 (16 lines per 256B row)
    int rowj[4], lsegj[4]; u32 offR[4]; size_t offGs[4]; const __half* pB1j[4];
#pragma unroll
    for (int j = 0; j < 4; ++j) {
        int local = tid + j * 256;
        rowj[j] = local >> 4; lsegj[j] = local & 15;
        offR[j] = (u32)rowj[j] * (RPK * 2) + (u32)lsegj[j] * 16;
        offGs[j] = (size_t)rowj[j] * HH + lsegj[j] * 8;
        int jj = rowj[j] & 31;
        int mat = (rowj[j] < 32) ? 1 : 0;
        pB1j[j] = g_Wt + ((size_t)mat * G4 + ((size_t)(jj >> 3) << 10) + u0 + (jj & 7)) * HH
                  + lsegj[j] * 8;
    }

    const int wlo = (w < 4) ? w : (w - 4);
    const int wm = (wlo >> 1) * 32;
    const int wn = (w < 4) ? ((wlo & 1) * 32) : ((wlo & 1) * 16);

    const u32 bufstr = 64 * RPK * 2;
    const u32 baseA1 = (u32)__cvta_generic_to_shared(&sm->A1[0][0][0]);
    const u32 baseA2 = (u32)__cvta_generic_to_shared(&sm->A2[0][0][0]);
    const u32 baseB1 = (u32)__cvta_generic_to_shared(&sm->B1[0][0][0]);
    const u32 baseB2 = (u32)__cvta_generic_to_shared(&sm->B2r[0][0]);
    const u32 offA_0 = (u32)(wm + (lg & 1) * 8 + lr) * (RPK * 2) + (lg >> 1) * 16;
    const u32 offA_1 = offA_0 + 16 * (RPK * 2);
    const u32 offB1_0 = (u32)(wn + (lg >> 1) * 8 + lr) * (RPK * 2) + (lg & 1) * 16;
    const u32 offB1_1 = offB1_0 + 16 * (RPK * 2);
    const u32 offB2  = (u32)(wn + (lg >> 1) * 8 + lr) * (PK2 * 2) + (lg & 1) * 16;

    // resident U1 slice
#pragma unroll
    for (int i = 0; i < 16; ++i) {
        int lin = tid + i * 256;
        int row = lin >> 7, seg = (lin & 127) * 8;
        size_t c = ((size_t)2 * G4 + ((row >> 3) << 10) + u0 + (row & 7));
        *(uint4*)&sm->B2r[row][seg] = *(const uint4*)(g_Wt + c * HH + seg);
    }
    for (int i = tid; i < 8 * 66; i += 256) {
        ((float*)sm->c0)[i] = 0.f;
        ((float*)sm->c1)[i] = 0.f;
    }
    __syncthreads();
#pragma unroll
    for (int half = 0; half < 2; ++half) {
        int b = cb + half * 32;
        size_t base = ((size_t)b * SS) * G4 + u0 + cu;
        float pi = g_P0[base + 1024];
        float pg = g_P0[base + 2048];
        float po = g_P0[base + 3072];
        float cn = sigf(pi) * tanha(pg);
        sm->c0[cu][b] = cn;
        g_h0[0][b * HH + u0 + cu] = __float2half(sigf(po) * tanha(cn));
    }
    unsigned epoch = 0;
    gbar(epoch);

    for (int t = 0; t < SS; ++t) {
        const __half* h0r = g_h0[t & 1];
        const __half* h1r = g_h1[(t + 1) & 1];
        __half* h0w = g_h0[(t + 1) & 1];
        __half* h1w = g_h1[t & 1];

        // ---- P prefetch into registers (overlapped with the whole GEMM) ----
        float2 pP[2][4][2];
        const bool isL1p = (w < 4) && (wn == 0);
        const bool isL0p = (w < 4) && (wn != 0) && (t < SS - 1);
        if (isL1p || isL0p) {
            const float* Pb = isL1p ? g_P1 : g_P0;
            const int tt = isL1p ? t : t + 1;
#pragma unroll
            for (int mt = 0; mt < 2; ++mt) {
                int r0 = wm + mt * 16 + g;
#pragma unroll
                for (int nt = 0; nt < 4; ++nt) {
                    int cj = nt * 8 + q2;
                    int gate = cj >> 3, un = cj & 7;
                    const float* base = Pb + ((size_t)gate << 10) + u0 + un;
                    pP[mt][nt][0] = *(const float2*)(base + ((size_t)r0 * SS + tt) * G4);
                    pP[mt][nt][1] = *(const float2*)(base + ((size_t)(r0 + 8) * SS + tt) * G4);
                }
            }
        }

        float acc[2][4][4];
#pragma unroll
        for (int a = 0; a < 2; ++a)
#pragma unroll
            for (int b = 0; b < 4; ++b)
#pragma unroll
                for (int c = 0; c < 4; ++c) acc[a][b][c] = 0.f;

        // prefill chunk 0 (buf 0)
#pragma unroll
        for (int j = 0; j < 4; ++j) {
            cpa16u(baseA1 + offR[j], h0r + offGs[j]);
            cpa16u(baseA2 + offR[j], h1r + offGs[j]);
            cpa16u(baseB1 + offR[j], pB1j[j]);
        }
        CP_COMMIT();

        for (int ch = 0; ch < RNCH; ++ch) {
            asm volatile("cp.async.wait_group 0;\n" ::: "memory");
            __syncthreads();
            if (ch + 1 < RNCH) {
                const u32 bo2 = (u32)((ch + 1) & 1) * bufstr;
                const int kc = (ch + 1) * RKC;
#pragma unroll
                for (int j = 0; j < 4; ++j) {
                    cpa16u(baseA1 + bo2 + offR[j], h0r + offGs[j] + kc);
                    cpa16u(baseA2 + bo2 + offR[j], h1r + offGs[j] + kc);
                    cpa16u(baseB1 + bo2 + offR[j], pB1j[j] + kc);
                }
                CP_COMMIT();
            }
            const u32 bo = (u32)(ch & 1) * bufstr;
            if (w < 4) {
#pragma unroll
                for (int kk = 0; kk < 8; ++kk) {
                    const u32 kb2 = kk * 32;
                    u32 a[2][4], bA[4], bB[4];
                    ldsm4(a[0][0], a[0][1], a[0][2], a[0][3], baseA1 + bo + offA_0 + kb2);
                    ldsm4(a[1][0], a[1][1], a[1][2], a[1][3], baseA1 + bo + offA_1 + kb2);
                    ldsm4(bA[0], bA[1], bA[2], bA[3], baseB1 + bo + offB1_0 + kb2);
                    ldsm4(bB[0], bB[1], bB[2], bB[3], baseB1 + bo + offB1_1 + kb2);
#pragma unroll
                    for (int nt = 0; nt < 4; ++nt) {
                        u32 b0 = (nt < 2) ? bA[(nt & 1) * 2]     : bB[(nt & 1) * 2];
                        u32 b1 = (nt < 2) ? bA[(nt & 1) * 2 + 1] : bB[(nt & 1) * 2 + 1];
                        mma_h(acc[0][nt], a[0][0], a[0][1], a[0][2], a[0][3], b0, b1);
                        mma_h(acc[1][nt], a[1][0], a[1][1], a[1][2], a[1][3], b0, b1);
                    }
                }
            } else {
                const u32 kgl2 = (u32)(ch * RKC) * 2;
#pragma unroll
                for (int kk = 0; kk < 8; ++kk) {
                    const u32 kb2 = kk * 32;
                    u32 a[2][4], bA[4];
                    ldsm4(a[0][0], a[0][1], a[0][2], a[0][3], baseA2 + bo + offA_0 + kb2);
                    ldsm4(a[1][0], a[1][1], a[1][2], a[1][3], baseA2 + bo + offA_1 + kb2);
                    ldsm4(bA[0], bA[1], bA[2], bA[3], baseB2 + offB2 + kgl2 + kb2);
#pragma unroll
                    for (int nt = 0; nt < 2; ++nt) {
                        u32 b0 = bA[nt * 2], b1 = bA[nt * 2 + 1];
                        mma_h(acc[0][nt], a[0][0], a[0][1], a[0][2], a[0][3], b0, b1);
                        mma_h(acc[1][nt], a[1][0], a[1][1], a[1][2], a[1][3], b0, b1);
                    }
                }
            }
        }

        // ---- epilogue (single phase: disjoint buffers, no extra sync) ----
        if (w < 4) {
            const bool isL1 = (wn == 0);
#pragma unroll
            for (int mt = 0; mt < 2; ++mt) {
                int r0 = wm + mt * 16 + g;
#pragma unroll
                for (int nt = 0; nt < 4; ++nt) {
                    int cj = nt * 8 + q2;
                    if (isL1) {
                        sm->pre1[cj][r0]         = acc[mt][nt][0] + pP[mt][nt][0].x;
                        sm->pre1[cj + 1][r0]     = acc[mt][nt][1] + pP[mt][nt][0].y;
                        sm->pre1[cj][r0 + 8]     = acc[mt][nt][2] + pP[mt][nt][1].x;
                        sm->pre1[cj + 1][r0 + 8] = acc[mt][nt][3] + pP[mt][nt][1].y;
                    } else if (t < SS - 1) {
                        sm->pre0[cj][r0]         = acc[mt][nt][0] + pP[mt][nt][0].x;
                        sm->pre0[cj + 1][r0]     = acc[mt][nt][1] + pP[mt][nt][0].y;
                        sm->pre0[cj][r0 + 8]     = acc[mt][nt][2] + pP[mt][nt][1].x;
                        sm->pre0[cj + 1][r0 + 8] = acc[mt][nt][3] + pP[mt][nt][1].y;
                    }
                }
            }
        } else {
#pragma unroll
            for (int mt = 0; mt < 2; ++mt) {
                int r0 = wm + mt * 16 + g;
#pragma unroll
                for (int nt = 0; nt < 2; ++nt) {
                    int cj = wn + nt * 8 + q2;
                    sm->pre1b[cj][r0]         = acc[mt][nt][0];
                    sm->pre1b[cj + 1][r0]     = acc[mt][nt][1];
                    sm->pre1b[cj][r0 + 8]     = acc[mt][nt][2];
                    sm->pre1b[cj + 1][r0 + 8] = acc[mt][nt][3];
                }
            }
        }
        __syncthreads();

        // ---- cells ----
#pragma unroll
        for (int half = 0; half < 2; ++half) {
            int b = cb + half * 32;
            {
                float f  = sigf(sm->pre1[cu][b]      + sm->pre1b[cu][b]);
                float ii = sigf(sm->pre1[8 + cu][b]  + sm->pre1b[8 + cu][b]);
                float gg = tanha(sm->pre1[16 + cu][b] + sm->pre1b[16 + cu][b]);
                float oo = sigf(sm->pre1[24 + cu][b] + sm->pre1b[24 + cu][b]);
                float cn = f * sm->c1[cu][b] + ii * gg;
                sm->c1[cu][b] = cn;
                float h = oo * tanha(cn);
                h1w[b * HH + u0 + cu] = __float2half(h);
                g_Hout[((size_t)b * SS + t) * HH + u0 + cu] = h;
                if (t == SS - 1) {
                    out[98304 + 65536 + b * HH + u0 + cu] = h;
                    out[229376 + 65536 + b * HH + u0 + cu] = cn;
                }
            }
            if (t < SS - 1) {
                float f  = sigf(sm->pre0[cu][b]);
                float ii = sigf(sm->pre0[8 + cu][b]);
                float gg = tanha(sm->pre0[16 + cu][b]);
                float oo = sigf(sm->pre0[24 + cu][b]);
                float cn = f * sm->c0[cu][b] + ii * gg;
                sm->c0[cu][b] = cn;
                float h = oo * tanha(cn);
                h0w[b * HH + u0 + cu] = __float2half(h);
                if (t == SS - 2) {
                    out[98304 + b * HH + u0 + cu] = h;
                    out[229376 + b * HH + u0 + cu] = cn;
                }
            }
        }
        gbar(epoch);
    }
}

__global__ void __launch_bounds__(256)
head_kernel(const float* __restrict__ fcW, const float* __restrict__ fcb,
            float* __restrict__ out)
{
    int warp = (blockIdx.x * blockDim.x + threadIdx.x) >> 5;
    int lane = threadIdx.x & 31;
    if (warp >= BB * SS) return;
    const float* hrow = &g_Hout[(size_t)warp * HH];
    float a0 = 0.f, a1 = 0.f, a2 = 0.f;
    for (int k = lane; k < HH; k += 32) {
        float h = __ldg(&hrow[k]);
        a0 += h * __ldg(&fcW[k * 3 + 0]);
        a1 += h * __ldg(&fcW[k * 3 + 1]);
        a2 += h * __ldg(&fcW[k * 3 + 2]);
    }
#pragma unroll
    for (int off = 16; off; off >>= 1) {
        a0 += __shfl_xor_sync(0xffffffffu, a0, off);
        a1 += __shfl_xor_sync(0xffffffffu, a1, off);
        a2 += __shfl_xor_sync(0xffffffffu, a2, off);
    }
    if (lane == 0) {
        out[warp * 3 + 0] = a0 + __ldg(&fcb[0]);
        out[warp * 3 + 1] = a1 + __ldg(&fcb[1]);
        out[warp * 3 + 2] = a2 + __ldg(&fcb[2]);
    }
}

extern "C" void kernel_launch(void* const* d_in, const int* in_sizes, int n_in,
                              void* d_out, int out_size)
{
    const float* x    = (const float*)d_in[0];
    const float* z    = (const float*)d_in[1];
    const float* W0   = (const float*)d_in[2];
    const float* bW0  = (const float*)d_in[3];
    const float* U0   = (const float*)d_in[4];
    const float* V0   = (const float*)d_in[5];
    const float* b0   = (const float*)d_in[6];
    const float* W1   = (const float*)d_in[7];
    const float* bW1  = (const float*)d_in[8];
    const float* U1   = (const float*)d_in[9];
    const float* V1   = (const float*)d_in[10];
    const float* b1   = (const float*)d_in[11];
    const float* fcW  = (const float*)d_in[12];
    const float* fcb  = (const float*)d_in[13];
    float* out = (float*)d_out;

    static int smem_set = 0;
    if (!smem_set) {
        cudaFuncSetAttribute(recur_kernel, cudaFuncAttributeMaxDynamicSharedMemorySize,
                             REC_SMEM_BYTES);
        cudaFuncSetAttribute(gemm_mma_kernel, cudaFuncAttributeMaxDynamicSharedMemorySize,
                             G_SMEM_BYTES);
        smem_set = 1;
    }

    prep2a_kernel<<<2048, 256>>>(x, z);
    prep_all_kernel<<<dim3(64, 16, 6), 256>>>(U0, W1, U1, W0, V0, V1);
    gemm_mma_kernel<<<dim3(64, 512, 2), 256, G_SMEM_BYTES>>>(bW0, b0, bW1, b1);
    recur_kernel<<<NCTA, 256, REC_SMEM_BYTES>>>(out);
    head_kernel<<<4096, 256>>>(fcW, fcb, out);
}

// round 15
// speedup vs baseline: 1.1399x; 1.0007x over previous
#include <cuda_runtime.h>
#include <cuda_fp16.h>
#include <math.h>

#define BB   64
#define SS   512
#define HH   1024
#define G4   4096
#define NCTA 128
#define KC   64
#define PK   72
#define PK2  1032
#define KA   640
#define RKC  128
#define RNCH 8
#define RPK  136

typedef unsigned int u32;

__device__ __half g_P0[BB * SS * G4];
__device__ __half g_P1[BB * SS * G4];
__device__ float g_Hout[BB * SS * HH];
__device__ __half g_Wt[3ULL * G4 * HH];   // recur weights [mat][col][k]
__device__ __half g_A[BB * SS * KA];      // [r][640] = [x|z] fp16
__device__ __half g_B0[G4 * KA];          // [n][640] = [W0|V0]^T fp16
__device__ __half g_B1[G4 * 128];         // [n][128] = V1^T fp16
__device__ __half g_h0[2][BB * HH];
__device__ __half g_h1[2][BB * HH];
__device__ unsigned g_bar;

__device__ __forceinline__ float4 ldg4(const float* p)  { return __ldg((const float4*)p); }
__device__ __forceinline__ float sigf(float x)  { return 1.0f / (1.0f + __expf(-x)); }
__device__ __forceinline__ float tanha(float x) { return 1.0f - 2.0f / (__expf(2.0f * x) + 1.0f); }

__device__ __forceinline__ void mma_h(float* c, u32 a0, u32 a1, u32 a2, u32 a3,
                                      u32 b0, u32 b1)
{
    asm volatile(
        "mma.sync.aligned.m16n8k16.row.col.f32.f16.f16.f32 "
        "{%0,%1,%2,%3}, {%4,%5,%6,%7}, {%8,%9}, {%0,%1,%2,%3};\n"
        : "+f"(c[0]), "+f"(c[1]), "+f"(c[2]), "+f"(c[3])
        : "r"(a0), "r"(a1), "r"(a2), "r"(a3), "r"(b0), "r"(b1));
}
__device__ __forceinline__ void ldsm4(u32& r0, u32& r1, u32& r2, u32& r3, u32 a)
{
    asm volatile("ldmatrix.sync.aligned.m8n8.x4.shared.b16 {%0,%1,%2,%3}, [%4];\n"
                 : "=r"(r0), "=r"(r1), "=r"(r2), "=r"(r3) : "r"(a));
}
__device__ __forceinline__ void cpa16(void* dst, const void* src) {
    u32 d = (u32)__cvta_generic_to_shared(dst);
    asm volatile("cp.async.cg.shared.global [%0], [%1], 16;\n" :: "r"(d), "l"(src));
}
__device__ __forceinline__ void cpa16u(u32 dst, const void* src) {
    asm volatile("cp.async.cg.shared.global [%0], [%1], 16;\n" :: "r"(dst), "l"(src));
}
#define CP_COMMIT() asm volatile("cp.async.commit_group;\n" ::: "memory")

// ---------------- prep2a + init (merged) -------------------------------------
__global__ void __launch_bounds__(256)
prep2a_kernel(const float* __restrict__ x, const float* __restrict__ z)
{
    size_t gtid = (size_t)blockIdx.x * blockDim.x + threadIdx.x;
    size_t stride = (size_t)gridDim.x * blockDim.x;
    __half hz = __float2half(0.f);
    for (size_t i = gtid; i < BB * HH; i += stride) {
        g_h0[0][i] = hz; g_h0[1][i] = hz;
        g_h1[0][i] = hz; g_h1[1][i] = hz;
    }
    if (gtid == 0) g_bar = 0u;
    size_t total = (size_t)BB * SS * KA;
    for (size_t idx = gtid; idx < total; idx += stride) {
        size_t r = idx / KA;
        int k = (int)(idx - r * KA);
        float v = (k < 512) ? __ldg(&x[r * 512 + k]) : __ldg(&z[r * 128 + (k - 512)]);
        g_A[idx] = __float2half(v);
    }
}

// ---------------- prep_all (merged transpose kernels) ------------------------
__global__ void __launch_bounds__(256)
prep_all_kernel(const float* __restrict__ U0, const float* __restrict__ W1,
                const float* __restrict__ U1, const float* __restrict__ W0,
                const float* __restrict__ V0, const float* __restrict__ V1)
{
    int zi = blockIdx.z;
    __shared__ float tile[64][65];
    int tid = threadIdx.x;
    if (zi < 3) {
        const float* src = (zi == 0) ? U0 : ((zi == 1) ? W1 : U1);
        int c0 = blockIdx.x * 64;
        int k0 = blockIdx.y * 64;
#pragma unroll
        for (int i = 0; i < 4; ++i) {
            int lin = tid + i * 256;
            int kr = lin >> 4, cq = lin & 15;
            float4 v = ldg4(src + (size_t)(k0 + kr) * G4 + c0 + cq * 4);
            tile[kr][cq * 4 + 0] = v.x; tile[kr][cq * 4 + 1] = v.y;
            tile[kr][cq * 4 + 2] = v.z; tile[kr][cq * 4 + 3] = v.w;
        }
        __syncthreads();
#pragma unroll
        for (int i = 0; i < 2; ++i) {
            int lin = tid + i * 256;
            int cr = lin >> 3, seg = (lin & 7) * 8;
            __half tmp[8];
#pragma unroll
            for (int j = 0; j < 8; ++j) tmp[j] = __float2half(tile[seg + j][cr]);
            *(uint4*)(g_Wt + ((size_t)zi * G4 + c0 + cr) * HH + k0 + seg) = *(uint4*)tmp;
        }
        return;
    }
    int which = zi - 3;
    if (which == 0) { if (blockIdx.y >= 8) return; }
    else            { if (blockIdx.y >= 2) return; }
    const float* W = (which == 0) ? W0 : ((which == 1) ? V0 : V1);
    int n0 = blockIdx.x * 64;
    int k0 = blockIdx.y * 64;
#pragma unroll
    for (int i = 0; i < 4; ++i) {
        int lin = tid + i * 256;
        int kr = lin >> 4, nq = lin & 15;
        float4 v = ldg4(W + (size_t)(k0 + kr) * G4 + n0 + nq * 4);
        tile[kr][nq * 4 + 0] = v.x; tile[kr][nq * 4 + 1] = v.y;
        tile[kr][nq * 4 + 2] = v.z; tile[kr][nq * 4 + 3] = v.w;
    }
    __syncthreads();
    __half* dst; int ldb, kb;
    if (which == 0)      { dst = g_B0; ldb = KA;  kb = k0; }
    else if (which == 1) { dst = g_B0; ldb = KA;  kb = 512 + k0; }
    else                 { dst = g_B1; ldb = 128; kb = k0; }
#pragma unroll
    for (int i = 0; i < 2; ++i) {
        int lin = tid + i * 256;
        int nr = lin >> 3, seg = (lin & 7) * 8;
        __half th[8];
#pragma unroll
        for (int j = 0; j < 8; ++j) th[j] = __float2half(tile[seg + j][nr]);
        *(uint4*)(dst + (size_t)(n0 + nr) * ldb + kb + seg) = *(uint4*)th;
    }
}

// ---------------- precompute GEMM: fp16, half output -------------------------
struct GSmem {
    __half A[3][64][PK];
    __half B[3][64][PK];
};
#define G_SMEM_BYTES ((int)sizeof(GSmem))

__global__ void __launch_bounds__(256, 2)
gemm_mma_kernel(const float* __restrict__ bsA1, const float* __restrict__ bsA2,
                const float* __restrict__ bsB1, const float* __restrict__ bsB2)
{
    const int which = blockIdx.z;
    const __half* __restrict__ A; const __half* __restrict__ B;
    const float* bs1; const float* bs2;
    int ldb, K; __half* OUT;
    if (which == 0) { A = g_A;       B = g_B0; ldb = KA;  K = KA;  OUT = g_P0; bs1 = bsA1; bs2 = bsA2; }
    else            { A = g_A + 512; B = g_B1; ldb = 128; K = 128; OUT = g_P1; bs1 = bsB1; bs2 = bsB2; }
    const int lda = KA;

    extern __shared__ unsigned char smraw[];
    GSmem* sm = (GSmem*)smraw;
    const int tid = threadIdx.x;
    const int n0 = blockIdx.x * 64;
    const int m0 = blockIdx.y * 64;
    const int lane = tid & 31, w = tid >> 5;
    const int g = lane >> 2, q2 = (lane & 3) * 2;
    const int lg = lane >> 3, lr = lane & 7;
    const int wm = (w >> 2) * 32;
    const int wn = (w & 3) * 16;
    const int nch = K / KC;

    const int l0 = tid * 2, l1 = tid * 2 + 1;
    const int ar0 = l0 >> 3, as0 = (l0 & 7) * 8;
    const int ar1 = l1 >> 3, as1 = (l1 & 7) * 8;

    const u32 bufstr = 64 * PK * 2;
    const u32 baseA = (u32)__cvta_generic_to_shared(&sm->A[0][0][0]);
    const u32 baseB = (u32)__cvta_generic_to_shared(&sm->B[0][0][0]);
    const u32 offA0 = (u32)(wm + (lg & 1) * 8 + lr) * (PK * 2) + (lg >> 1) * 16;
    const u32 offA1 = offA0 + 16 * (PK * 2);
    const u32 offB  = (u32)(wn + (lg >> 1) * 8 + lr) * (PK * 2) + (lg & 1) * 16;

    float acc[2][2][4];
#pragma unroll
    for (int a = 0; a < 2; ++a)
#pragma unroll
        for (int b = 0; b < 2; ++b)
#pragma unroll
            for (int c = 0; c < 4; ++c) acc[a][b][c] = 0.f;

#pragma unroll
    for (int pc = 0; pc < 2; ++pc) {
        int k0 = pc * KC;
        cpa16(&sm->A[pc][ar0][as0], A + (size_t)(m0 + ar0) * lda + k0 + as0);
        cpa16(&sm->A[pc][ar1][as1], A + (size_t)(m0 + ar1) * lda + k0 + as1);
        cpa16(&sm->B[pc][ar0][as0], B + (size_t)(n0 + ar0) * ldb + k0 + as0);
        cpa16(&sm->B[pc][ar1][as1], B + (size_t)(n0 + ar1) * ldb + k0 + as1);
        CP_COMMIT();
    }

    for (int ch = 0; ch < nch; ++ch) {
        if (ch < nch - 1) asm volatile("cp.async.wait_group 1;\n" ::: "memory");
        else              asm volatile("cp.async.wait_group 0;\n" ::: "memory");
        __syncthreads();
        if (ch + 2 < nch) {
            int buf = (ch + 2) % 3;
            int k0 = (ch + 2) * KC;
            cpa16(&sm->A[buf][ar0][as0], A + (size_t)(m0 + ar0) * lda + k0 + as0);
            cpa16(&sm->A[buf][ar1][as1], A + (size_t)(m0 + ar1) * lda + k0 + as1);
            cpa16(&sm->B[buf][ar0][as0], B + (size_t)(n0 + ar0) * ldb + k0 + as0);
            cpa16(&sm->B[buf][ar1][as1], B + (size_t)(n0 + ar1) * ldb + k0 + as1);
            CP_COMMIT();
        }
        const int buf = ch % 3;
        const u32 bo = buf * bufstr;
#pragma unroll
        for (int kk = 0; kk < 4; ++kk) {
            const u32 kb2 = kk * 32;
            u32 a[2][4], b[4];
            ldsm4(a[0][0], a[0][1], a[0][2], a[0][3], baseA + bo + offA0 + kb2);
            ldsm4(a[1][0], a[1][1], a[1][2], a[1][3], baseA + bo + offA1 + kb2);
            ldsm4(b[0], b[1], b[2], b[3], baseB + bo + offB + kb2);
#pragma unroll
            for (int nt = 0; nt < 2; ++nt)
#pragma unroll
                for (int mt = 0; mt < 2; ++mt)
                    mma_h(acc[mt][nt], a[mt][0], a[mt][1], a[mt][2], a[mt][3],
                          b[nt * 2], b[nt * 2 + 1]);
        }
    }

#pragma unroll
    for (int mt = 0; mt < 2; ++mt) {
        int r0 = m0 + wm + mt * 16 + g;
#pragma unroll
        for (int nt = 0; nt < 2; ++nt) {
            int c = n0 + wn + nt * 8 + q2;
            float b0 = __ldg(&bs1[c]) + __ldg(&bs2[c]);
            float b1 = __ldg(&bs1[c + 1]) + __ldg(&bs2[c + 1]);
            *(__half2*)&OUT[(size_t)r0 * G4 + c] =
                __floats2half2_rn(acc[mt][nt][0] + b0, acc[mt][nt][1] + b1);
            *(__half2*)&OUT[(size_t)(r0 + 8) * G4 + c] =
                __floats2half2_rn(acc[mt][nt][2] + b0, acc[mt][nt][3] + b1);
        }
    }
}

__device__ __forceinline__ void gbar(unsigned& epoch)
{
    __syncthreads();
    epoch += NCTA;
    if (threadIdx.x == 0) {
        __threadfence();
        atomicAdd(&g_bar, 1u);
        while (*(volatile unsigned*)&g_bar < epoch) { }
        __threadfence();
    }
    __syncthreads();
}

// ---------------- recurrent: U0+U1 resident, W1 streamed, half P -------------
struct RecSmem {
    __half A1[2][64][RPK];
    __half A2[2][64][RPK];
    __half B1w[2][32][RPK];   // streamed W1 slice
    __half U0r[32][PK2];      // resident U0 slice
    __half U1r[32][PK2];      // resident U1 slice
    float pre[32][66];        // reused: layer1 then layer0
};
#define REC_SMEM_BYTES ((int)sizeof(RecSmem))

__global__ void __launch_bounds__(256, 1)
recur_kernel(float* __restrict__ out)
{
    extern __shared__ unsigned char smraw[];
    RecSmem* sm = (RecSmem*)smraw;

    const int tid = threadIdx.x;
    const int u0 = blockIdx.x * 8;
    const int lane = tid & 31, w = tid >> 5;
    const int g = lane >> 2, q2 = (lane & 3) * 2;
    const int lg = lane >> 3, lr = lane & 7;
    const int cu = tid & 7, cb = tid >> 3;

    const u32 baseA1 = (u32)__cvta_generic_to_shared(&sm->A1[0][0][0]);
    const u32 baseA2 = (u32)__cvta_generic_to_shared(&sm->A2[0][0][0]);
    const u32 baseBw = (u32)__cvta_generic_to_shared(&sm->B1w[0][0][0]);
    const u32 baseU0 = (u32)__cvta_generic_to_shared(&sm->U0r[0][0]);
    const u32 baseU1 = (u32)__cvta_generic_to_shared(&sm->U1r[0][0]);

    // staging: 10 lines/thread over [A1(1024) | A2(1024) | B1w(512)]
    int kindv[10]; u32 dst0[10], bstr[10]; size_t offGv[10]; const __half* pWv[10];
#pragma unroll
    for (int j = 0; j < 10; ++j) {
        int lin = tid + j * 256;
        if (lin < 2048) {
            int kind = lin >> 10;
            int local = lin & 1023;
            int row = local >> 4, seg = local & 15;
            kindv[j] = kind;
            dst0[j] = (kind ? baseA2 : baseA1) + (u32)row * (RPK * 2) + (u32)seg * 16;
            bstr[j] = 64 * RPK * 2;
            offGv[j] = (size_t)row * HH + seg * 8;
            pWv[j] = 0;
        } else {
            int local = lin - 2048;
            int row = local >> 4, seg = local & 15;
            kindv[j] = 2;
            dst0[j] = baseBw + (u32)row * (RPK * 2) + (u32)seg * 16;
            bstr[j] = 32 * RPK * 2;
            offGv[j] = 0;
            pWv[j] = g_Wt + ((size_t)1 * G4 + ((size_t)(row >> 3) << 10) + u0 + (row & 7)) * HH
                     + seg * 8;
        }
    }

    const int wlo = (w < 4) ? w : (w - 4);
    const int wm = (wlo >> 1) * 32;
    const int wn = (w < 4) ? ((wlo & 1) * 32) : ((wlo & 1) * 16);

    const u32 offA_0 = (u32)(wm + (lg & 1) * 8 + lr) * (RPK * 2) + (lg >> 1) * 16;
    const u32 offA_1 = offA_0 + 16 * (RPK * 2);
    const u32 offBw_0 = (u32)((lg >> 1) * 8 + lr) * (RPK * 2) + (lg & 1) * 16;
    const u32 offBw_1 = offBw_0 + 16 * (RPK * 2);
    const u32 offU0_0 = (u32)((lg >> 1) * 8 + lr) * (PK2 * 2) + (lg & 1) * 16;
    const u32 offU0_1 = offU0_0 + 16 * (PK2 * 2);
    const u32 offU1  = (u32)(wn + (lg >> 1) * 8 + lr) * (PK2 * 2) + (lg & 1) * 16;

    // resident fills: U0r (mat 0) + U1r (mat 2)
    for (int lin = tid; lin < 8192; lin += 256) {
        int arr = lin >> 12;                 // 0 = U0r, 1 = U1r
        int local = lin & 4095;
        int row = local >> 7, seg = (local & 127) * 8;
        size_t mat = arr ? 2 : 0;
        size_t c = (mat * G4 + ((size_t)(row >> 3) << 10) + u0 + (row & 7));
        __half* dst = arr ? &sm->U1r[row][seg] : &sm->U0r[row][seg];
        *(uint4*)dst = *(const uint4*)(g_Wt + c * HH + seg);
    }
    float c0r[2] = {0.f, 0.f}, c1r[2] = {0.f, 0.f};
    __syncthreads();
    // prologue: layer0(t=0)
#pragma unroll
    for (int half = 0; half < 2; ++half) {
        int b = cb + half * 32;
        size_t base = ((size_t)b * SS) * G4 + u0 + cu;
        float pi = __half2float(g_P0[base + 1024]);
        float pg = __half2float(g_P0[base + 2048]);
        float po = __half2float(g_P0[base + 3072]);
        float cn = sigf(pi) * tanha(pg);
        c0r[half] = cn;
        g_h0[0][b * HH + u0 + cu] = __float2half(sigf(po) * tanha(cn));
    }
    unsigned epoch = 0;
    gbar(epoch);

    for (int t = 0; t < SS; ++t) {
        const __half* h0r = g_h0[t & 1];
        const __half* h1r = g_h1[(t + 1) & 1];
        __half* h0w = g_h0[(t + 1) & 1];
        __half* h1w = g_h1[t & 1];

        // ---- P prefetch (half2) into registers ----
        float2 pP[2][4][2];
        const bool isL1p = (w < 4) && (wn == 0);
        const bool isL0p = (w < 4) && (wn != 0) && (t < SS - 1);
        if (isL1p || isL0p) {
            const __half* Pb = isL1p ? g_P1 : g_P0;
            const int tt = isL1p ? t : t + 1;
#pragma unroll
            for (int mt = 0; mt < 2; ++mt) {
                int r0 = wm + mt * 16 + g;
#pragma unroll
                for (int nt = 0; nt < 4; ++nt) {
                    int cj = nt * 8 + q2;
                    int gate = cj >> 3, un = cj & 7;
                    const __half* base = Pb + ((size_t)gate << 10) + u0 + un;
                    pP[mt][nt][0] = __half22float2(
                        *(const __half2*)(base + ((size_t)r0 * SS + tt) * G4));
                    pP[mt][nt][1] = __half22float2(
                        *(const __half2*)(base + ((size_t)(r0 + 8) * SS + tt) * G4));
                }
            }
        }

        float acc[2][4][4];
#pragma unroll
        for (int a = 0; a < 2; ++a)
#pragma unroll
            for (int b = 0; b < 4; ++b)
#pragma unroll
                for (int c = 0; c < 4; ++c) acc[a][b][c] = 0.f;

        // prefill chunk 0
#pragma unroll
        for (int j = 0; j < 10; ++j) {
            const __half* s = (kindv[j] == 0) ? (h0r + offGv[j])
                             : (kindv[j] == 1) ? (h1r + offGv[j]) : pWv[j];
            cpa16u(dst0[j], s);
        }
        CP_COMMIT();

        for (int ch = 0; ch < RNCH; ++ch) {
            asm volatile("cp.async.wait_group 0;\n" ::: "memory");
            __syncthreads();
            if (ch + 1 < RNCH) {
                const int kc = (ch + 1) * RKC;
                const u32 b2 = (u32)((ch + 1) & 1);
#pragma unroll
                for (int j = 0; j < 10; ++j) {
                    const __half* s = (kindv[j] == 0) ? (h0r + offGv[j])
                                     : (kindv[j] == 1) ? (h1r + offGv[j]) : pWv[j];
                    cpa16u(dst0[j] + b2 * bstr[j], s + kc);
                }
                CP_COMMIT();
            }
            const u32 boA = (u32)(ch & 1) * (64 * RPK * 2);
            const u32 boB = (u32)(ch & 1) * (32 * RPK * 2);
            const u32 kgl2 = (u32)(ch * RKC) * 2;
            if (w < 4) {
#pragma unroll
                for (int kk = 0; kk < 8; ++kk) {
                    const u32 kb2 = kk * 32;
                    u32 a[2][4], bA[4], bB[4];
                    ldsm4(a[0][0], a[0][1], a[0][2], a[0][3], baseA1 + boA + offA_0 + kb2);
                    ldsm4(a[1][0], a[1][1], a[1][2], a[1][3], baseA1 + boA + offA_1 + kb2);
                    if (wn == 0) {
                        ldsm4(bA[0], bA[1], bA[2], bA[3], baseBw + boB + offBw_0 + kb2);
                        ldsm4(bB[0], bB[1], bB[2], bB[3], baseBw + boB + offBw_1 + kb2);
                    } else {
                        ldsm4(bA[0], bA[1], bA[2], bA[3], baseU0 + offU0_0 + kgl2 + kb2);
                        ldsm4(bB[0], bB[1], bB[2], bB[3], baseU0 + offU0_1 + kgl2 + kb2);
                    }
#pragma unroll
                    for (int nt = 0; nt < 4; ++nt) {
                        u32 b0 = (nt < 2) ? bA[(nt & 1) * 2]     : bB[(nt & 1) * 2];
                        u32 b1 = (nt < 2) ? bA[(nt & 1) * 2 + 1] : bB[(nt & 1) * 2 + 1];
                        mma_h(acc[0][nt], a[0][0], a[0][1], a[0][2], a[0][3], b0, b1);
                        mma_h(acc[1][nt], a[1][0], a[1][1], a[1][2], a[1][3], b0, b1);
                    }
                }
            } else {
#pragma unroll
                for (int kk = 0; kk < 8; ++kk) {
                    const u32 kb2 = kk * 32;
                    u32 a[2][4], bA[4];
                    ldsm4(a[0][0], a[0][1], a[0][2], a[0][3], baseA2 + boA + offA_0 + kb2);
                    ldsm4(a[1][0], a[1][1], a[1][2], a[1][3], baseA2 + boA + offA_1 + kb2);
                    ldsm4(bA[0], bA[1], bA[2], bA[3], baseU1 + offU1 + kgl2 + kb2);
#pragma unroll
                    for (int nt = 0; nt < 2; ++nt) {
                        u32 b0 = bA[nt * 2], b1 = bA[nt * 2 + 1];
                        mma_h(acc[0][nt], a[0][0], a[0][1], a[0][2], a[0][3], b0, b1);
                        mma_h(acc[1][nt], a[1][0], a[1][1], a[1][2], a[1][3], b0, b1);
                    }
                }
            }
        }

        // ---- epilogue stage 1: layer1 main (wn==0 warps) ----
        if (w < 4 && wn == 0) {
#pragma unroll
            for (int mt = 0; mt < 2; ++mt) {
                int r0 = wm + mt * 16 + g;
#pragma unroll
                for (int nt = 0; nt < 4; ++nt) {
                    int cj = nt * 8 + q2;
                    sm->pre[cj][r0]         = acc[mt][nt][0] + pP[mt][nt][0].x;
                    sm->pre[cj + 1][r0]     = acc[mt][nt][1] + pP[mt][nt][0].y;
                    sm->pre[cj][r0 + 8]     = acc[mt][nt][2] + pP[mt][nt][1].x;
                    sm->pre[cj + 1][r0 + 8] = acc[mt][nt][3] + pP[mt][nt][1].y;
                }
            }
        }
        __syncthreads();
        // ---- stage 2: U1 add (warps 4-7) ----
        if (w >= 4) {
#pragma unroll
            for (int mt = 0; mt < 2; ++mt) {
                int r0 = wm + mt * 16 + g;
#pragma unroll
                for (int nt = 0; nt < 2; ++nt) {
                    int cj = wn + nt * 8 + q2;
                    sm->pre[cj][r0]         += acc[mt][nt][0];
                    sm->pre[cj + 1][r0]     += acc[mt][nt][1];
                    sm->pre[cj][r0 + 8]     += acc[mt][nt][2];
                    sm->pre[cj + 1][r0 + 8] += acc[mt][nt][3];
                }
            }
        }
        __syncthreads();
        // ---- cells layer 1 ----
#pragma unroll
        for (int half = 0; half < 2; ++half) {
            int b = cb + half * 32;
            float f  = sigf(sm->pre[cu][b]);
            float ii = sigf(sm->pre[8 + cu][b]);
            float gg = tanha(sm->pre[16 + cu][b]);
            float oo = sigf(sm->pre[24 + cu][b]);
            float cn = f * c1r[half] + ii * gg;
            c1r[half] = cn;
            float h = oo * tanha(cn);
            h1w[b * HH + u0 + cu] = __float2half(h);
            g_Hout[((size_t)b * SS + t) * HH + u0 + cu] = h;
            if (t == SS - 1) {
                out[98304 + 65536 + b * HH + u0 + cu] = h;
                out[229376 + 65536 + b * HH + u0 + cu] = cn;
            }
        }
        __syncthreads();
        // ---- stage 3: layer0 pre (wn==32 warps) ----
        if (w < 4 && wn == 32 && t < SS - 1) {
#pragma unroll
            for (int mt = 0; mt < 2; ++mt) {
                int r0 = wm + mt * 16 + g;
#pragma unroll
                for (int nt = 0; nt < 4; ++nt) {
                    int cj = nt * 8 + q2;
                    sm->pre[cj][r0]         = acc[mt][nt][0] + pP[mt][nt][0].x;
                    sm->pre[cj + 1][r0]     = acc[mt][nt][1] + pP[mt][nt][0].y;
                    sm->pre[cj][r0 + 8]     = acc[mt][nt][2] + pP[mt][nt][1].x;
                    sm->pre[cj + 1][r0 + 8] = acc[mt][nt][3] + pP[mt][nt][1].y;
                }
            }
        }
        __syncthreads();
        // ---- cells layer 0 ----
        if (t < SS - 1) {
#pragma unroll
            for (int half = 0; half < 2; ++half) {
                int b = cb + half * 32;
                float f  = sigf(sm->pre[cu][b]);
                float ii = sigf(sm->pre[8 + cu][b]);
                float gg = tanha(sm->pre[16 + cu][b]);
                float oo = sigf(sm->pre[24 + cu][b]);
                float cn = f * c0r[half] + ii * gg;
                c0r[half] = cn;
                float h = oo * tanha(cn);
                h0w[b * HH + u0 + cu] = __float2half(h);
                if (t == SS - 2) {
                    out[98304 + b * HH + u0 + cu] = h;
                    out[229376 + b * HH + u0 + cu] = cn;
                }
            }
        }
        gbar(epoch);
    }
}

__global__ void __launch_bounds__(256)
head_kernel(const float* __restrict__ fcW, const float* __restrict__ fcb,
            float* __restrict__ out)
{
    int warp = (blockIdx.x * blockDim.x + threadIdx.x) >> 5;
    int lane = threadIdx.x & 31;
    if (warp >= BB * SS) return;
    const float* hrow = &g_Hout[(size_t)warp * HH];
    float a0 = 0.f, a1 = 0.f, a2 = 0.f;
    for (int k = lane; k < HH; k += 32) {
        float h = __ldg(&hrow[k]);
        a0 += h * __ldg(&fcW[k * 3 + 0]);
        a1 += h * __ldg(&fcW[k * 3 + 1]);
        a2 += h * __ldg(&fcW[k * 3 + 2]);
    }
#pragma unroll
    for (int off = 16; off; off >>= 1) {
        a0 += __shfl_xor_sync(0xffffffffu, a0, off);
        a1 += __shfl_xor_sync(0xffffffffu, a1, off);
        a2 += __shfl_xor_sync(0xffffffffu, a2, off);
    }
    if (lane == 0) {
        out[warp * 3 + 0] = a0 + __ldg(&fcb[0]);
        out[warp * 3 + 1] = a1 + __ldg(&fcb[1]);
        out[warp * 3 + 2] = a2 + __ldg(&fcb[2]);
    }
}

extern "C" void kernel_launch(void* const* d_in, const int* in_sizes, int n_in,
                              void* d_out, int out_size)
{
    const float* x    = (const float*)d_in[0];
    const float* z    = (const float*)d_in[1];
    const float* W0   = (const float*)d_in[2];
    const float* bW0  = (const float*)d_in[3];
    const float* U0   = (const float*)d_in[4];
    const float* V0   = (const float*)d_in[5];
    const float* b0   = (const float*)d_in[6];
    const float* W1   = (const float*)d_in[7];
    const float* bW1  = (const float*)d_in[8];
    const float* U1   = (const float*)d_in[9];
    const float* V1   = (const float*)d_in[10];
    const float* b1   = (const float*)d_in[11];
    const float* fcW  = (const float*)d_in[12];
    const float* fcb  = (const float*)d_in[13];
    float* out = (float*)d_out;

    static int smem_set = 0;
    if (!smem_set) {
        cudaFuncSetAttribute(recur_kernel, cudaFuncAttributeMaxDynamicSharedMemorySize,
                             REC_SMEM_BYTES);
        cudaFuncSetAttribute(gemm_mma_kernel, cudaFuncAttributeMaxDynamicSharedMemorySize,
                             G_SMEM_BYTES);
        smem_set = 1;
    }

    prep2a_kernel<<<2048, 256>>>(x, z);
    prep_all_kernel<<<dim3(64, 16, 6), 256>>>(U0, W1, U1, W0, V0, V1);
    gemm_mma_kernel<<<dim3(64, 512, 2), 256, G_SMEM_BYTES>>>(bW0, b0, bW1, b1);
    recur_kernel<<<NCTA, 256, REC_SMEM_BYTES>>>(out);
    head_kernel<<<4096, 256>>>(fcW, fcb, out);
}

// round 16
// speedup vs baseline: 1.1977x; 1.0507x over previous
#include <cuda_runtime.h>
#include <cuda_fp16.h>
#include <math.h>

#define BB   64
#define SS   512
#define HH   1024
#define G4   4096
#define NCTA 128
#define KC   64
#define PK   72
#define PK2  1032
#define KA   640
#define RKC  128
#define RNCH 8
#define RPK  136

typedef unsigned int u32;

__device__ __half g_P0[BB * SS * G4];
__device__ __half g_P1[BB * SS * G4];
__device__ float g_Hout[BB * SS * HH];
__device__ __half g_Wt[3ULL * G4 * HH];   // recur weights [mat][col][k]
__device__ __half g_A[BB * SS * KA];      // [r][640] = [x|z] fp16
__device__ __half g_B0[G4 * KA];          // [n][640] = [W0|V0]^T fp16
__device__ __half g_B1[G4 * 128];         // [n][128] = V1^T fp16
__device__ __half g_h0[2][BB * HH];
__device__ __half g_h1[2][BB * HH];
__device__ unsigned g_bar;

__device__ __forceinline__ float4 ldg4(const float* p)  { return __ldg((const float4*)p); }
__device__ __forceinline__ float sigf(float x)  { return 1.0f / (1.0f + __expf(-x)); }
__device__ __forceinline__ float tanha(float x) { return 1.0f - 2.0f / (__expf(2.0f * x) + 1.0f); }

__device__ __forceinline__ void mma_h(float* c, u32 a0, u32 a1, u32 a2, u32 a3,
                                      u32 b0, u32 b1)
{
    asm volatile(
        "mma.sync.aligned.m16n8k16.row.col.f32.f16.f16.f32 "
        "{%0,%1,%2,%3}, {%4,%5,%6,%7}, {%8,%9}, {%0,%1,%2,%3};\n"
        : "+f"(c[0]), "+f"(c[1]), "+f"(c[2]), "+f"(c[3])
        : "r"(a0), "r"(a1), "r"(a2), "r"(a3), "r"(b0), "r"(b1));
}
__device__ __forceinline__ void ldsm4(u32& r0, u32& r1, u32& r2, u32& r3, u32 a)
{
    asm volatile("ldmatrix.sync.aligned.m8n8.x4.shared.b16 {%0,%1,%2,%3}, [%4];\n"
                 : "=r"(r0), "=r"(r1), "=r"(r2), "=r"(r3) : "r"(a));
}
__device__ __forceinline__ void cpa16(void* dst, const void* src) {
    u32 d = (u32)__cvta_generic_to_shared(dst);
    asm volatile("cp.async.cg.shared.global [%0], [%1], 16;\n" :: "r"(d), "l"(src));
}
__device__ __forceinline__ void cpa16u(u32 dst, const void* src) {
    asm volatile("cp.async.cg.shared.global [%0], [%1], 16;\n" :: "r"(dst), "l"(src));
}
#define CP_COMMIT() asm volatile("cp.async.commit_group;\n" ::: "memory")

// ---------------- prep2a + init (merged) -------------------------------------
__global__ void __launch_bounds__(256)
prep2a_kernel(const float* __restrict__ x, const float* __restrict__ z)
{
    size_t gtid = (size_t)blockIdx.x * blockDim.x + threadIdx.x;
    size_t stride = (size_t)gridDim.x * blockDim.x;
    __half hz = __float2half(0.f);
    for (size_t i = gtid; i < BB * HH; i += stride) {
        g_h0[0][i] = hz; g_h0[1][i] = hz;
        g_h1[0][i] = hz; g_h1[1][i] = hz;
    }
    if (gtid == 0) g_bar = 0u;
    size_t total = (size_t)BB * SS * KA;
    for (size_t idx = gtid; idx < total; idx += stride) {
        size_t r = idx / KA;
        int k = (int)(idx - r * KA);
        float v = (k < 512) ? __ldg(&x[r * 512 + k]) : __ldg(&z[r * 128 + (k - 512)]);
        g_A[idx] = __float2half(v);
    }
}

// ---------------- prep_all (merged transpose kernels) ------------------------
__global__ void __launch_bounds__(256)
prep_all_kernel(const float* __restrict__ U0, const float* __restrict__ W1,
                const float* __restrict__ U1, const float* __restrict__ W0,
                const float* __restrict__ V0, const float* __restrict__ V1)
{
    int zi = blockIdx.z;
    __shared__ float tile[64][65];
    int tid = threadIdx.x;
    if (zi < 3) {
        const float* src = (zi == 0) ? U0 : ((zi == 1) ? W1 : U1);
        int c0 = blockIdx.x * 64;
        int k0 = blockIdx.y * 64;
#pragma unroll
        for (int i = 0; i < 4; ++i) {
            int lin = tid + i * 256;
            int kr = lin >> 4, cq = lin & 15;
            float4 v = ldg4(src + (size_t)(k0 + kr) * G4 + c0 + cq * 4);
            tile[kr][cq * 4 + 0] = v.x; tile[kr][cq * 4 + 1] = v.y;
            tile[kr][cq * 4 + 2] = v.z; tile[kr][cq * 4 + 3] = v.w;
        }
        __syncthreads();
#pragma unroll
        for (int i = 0; i < 2; ++i) {
            int lin = tid + i * 256;
            int cr = lin >> 3, seg = (lin & 7) * 8;
            __half tmp[8];
#pragma unroll
            for (int j = 0; j < 8; ++j) tmp[j] = __float2half(tile[seg + j][cr]);
            *(uint4*)(g_Wt + ((size_t)zi * G4 + c0 + cr) * HH + k0 + seg) = *(uint4*)tmp;
        }
        return;
    }
    int which = zi - 3;
    if (which == 0) { if (blockIdx.y >= 8) return; }
    else            { if (blockIdx.y >= 2) return; }
    const float* W = (which == 0) ? W0 : ((which == 1) ? V0 : V1);
    int n0 = blockIdx.x * 64;
    int k0 = blockIdx.y * 64;
#pragma unroll
    for (int i = 0; i < 4; ++i) {
        int lin = tid + i * 256;
        int kr = lin >> 4, nq = lin & 15;
        float4 v = ldg4(W + (size_t)(k0 + kr) * G4 + n0 + nq * 4);
        tile[kr][nq * 4 + 0] = v.x; tile[kr][nq * 4 + 1] = v.y;
        tile[kr][nq * 4 + 2] = v.z; tile[kr][nq * 4 + 3] = v.w;
    }
    __syncthreads();
    __half* dst; int ldb, kb;
    if (which == 0)      { dst = g_B0; ldb = KA;  kb = k0; }
    else if (which == 1) { dst = g_B0; ldb = KA;  kb = 512 + k0; }
    else                 { dst = g_B1; ldb = 128; kb = k0; }
#pragma unroll
    for (int i = 0; i < 2; ++i) {
        int lin = tid + i * 256;
        int nr = lin >> 3, seg = (lin & 7) * 8;
        __half th[8];
#pragma unroll
        for (int j = 0; j < 8; ++j) th[j] = __float2half(tile[seg + j][nr]);
        *(uint4*)(dst + (size_t)(n0 + nr) * ldb + kb + seg) = *(uint4*)th;
    }
}

// ---------------- precompute GEMM: fp16, half output -------------------------
struct GSmem {
    __half A[3][64][PK];
    __half B[3][64][PK];
};
#define G_SMEM_BYTES ((int)sizeof(GSmem))

__global__ void __launch_bounds__(256, 2)
gemm_mma_kernel(const float* __restrict__ bsA1, const float* __restrict__ bsA2,
                const float* __restrict__ bsB1, const float* __restrict__ bsB2)
{
    const int which = blockIdx.z;
    const __half* __restrict__ A; const __half* __restrict__ B;
    const float* bs1; const float* bs2;
    int ldb, K; __half* OUT;
    if (which == 0) { A = g_A;       B = g_B0; ldb = KA;  K = KA;  OUT = g_P0; bs1 = bsA1; bs2 = bsA2; }
    else            { A = g_A + 512; B = g_B1; ldb = 128; K = 128; OUT = g_P1; bs1 = bsB1; bs2 = bsB2; }
    const int lda = KA;

    extern __shared__ unsigned char smraw[];
    GSmem* sm = (GSmem*)smraw;
    const int tid = threadIdx.x;
    const int n0 = blockIdx.x * 64;
    const int m0 = blockIdx.y * 64;
    const int lane = tid & 31, w = tid >> 5;
    const int g = lane >> 2, q2 = (lane & 3) * 2;
    const int lg = lane >> 3, lr = lane & 7;
    const int wm = (w >> 2) * 32;
    const int wn = (w & 3) * 16;
    const int nch = K / KC;

    const int l0 = tid * 2, l1 = tid * 2 + 1;
    const int ar0 = l0 >> 3, as0 = (l0 & 7) * 8;
    const int ar1 = l1 >> 3, as1 = (l1 & 7) * 8;

    const u32 bufstr = 64 * PK * 2;
    const u32 baseA = (u32)__cvta_generic_to_shared(&sm->A[0][0][0]);
    const u32 baseB = (u32)__cvta_generic_to_shared(&sm->B[0][0][0]);
    const u32 offA0 = (u32)(wm + (lg & 1) * 8 + lr) * (PK * 2) + (lg >> 1) * 16;
    const u32 offA1 = offA0 + 16 * (PK * 2);
    const u32 offB  = (u32)(wn + (lg >> 1) * 8 + lr) * (PK * 2) + (lg & 1) * 16;

    float acc[2][2][4];
#pragma unroll
    for (int a = 0; a < 2; ++a)
#pragma unroll
        for (int b = 0; b < 2; ++b)
#pragma unroll
            for (int c = 0; c < 4; ++c) acc[a][b][c] = 0.f;

#pragma unroll
    for (int pc = 0; pc < 2; ++pc) {
        int k0 = pc * KC;
        cpa16(&sm->A[pc][ar0][as0], A + (size_t)(m0 + ar0) * lda + k0 + as0);
        cpa16(&sm->A[pc][ar1][as1], A + (size_t)(m0 + ar1) * lda + k0 + as1);
        cpa16(&sm->B[pc][ar0][as0], B + (size_t)(n0 + ar0) * ldb + k0 + as0);
        cpa16(&sm->B[pc][ar1][as1], B + (size_t)(n0 + ar1) * ldb + k0 + as1);
        CP_COMMIT();
    }

    for (int ch = 0; ch < nch; ++ch) {
        if (ch < nch - 1) asm volatile("cp.async.wait_group 1;\n" ::: "memory");
        else              asm volatile("cp.async.wait_group 0;\n" ::: "memory");
        __syncthreads();
        if (ch + 2 < nch) {
            int buf = (ch + 2) % 3;
            int k0 = (ch + 2) * KC;
            cpa16(&sm->A[buf][ar0][as0], A + (size_t)(m0 + ar0) * lda + k0 + as0);
            cpa16(&sm->A[buf][ar1][as1], A + (size_t)(m0 + ar1) * lda + k0 + as1);
            cpa16(&sm->B[buf][ar0][as0], B + (size_t)(n0 + ar0) * ldb + k0 + as0);
            cpa16(&sm->B[buf][ar1][as1], B + (size_t)(n0 + ar1) * ldb + k0 + as1);
            CP_COMMIT();
        }
        const int buf = ch % 3;
        const u32 bo = buf * bufstr;
#pragma unroll
        for (int kk = 0; kk < 4; ++kk) {
            const u32 kb2 = kk * 32;
            u32 a[2][4], b[4];
            ldsm4(a[0][0], a[0][1], a[0][2], a[0][3], baseA + bo + offA0 + kb2);
            ldsm4(a[1][0], a[1][1], a[1][2], a[1][3], baseA + bo + offA1 + kb2);
            ldsm4(b[0], b[1], b[2], b[3], baseB + bo + offB + kb2);
#pragma unroll
            for (int nt = 0; nt < 2; ++nt)
#pragma unroll
                for (int mt = 0; mt < 2; ++mt)
                    mma_h(acc[mt][nt], a[mt][0], a[mt][1], a[mt][2], a[mt][3],
                          b[nt * 2], b[nt * 2 + 1]);
        }
    }

#pragma unroll
    for (int mt = 0; mt < 2; ++mt) {
        int r0 = m0 + wm + mt * 16 + g;
#pragma unroll
        for (int nt = 0; nt < 2; ++nt) {
            int c = n0 + wn + nt * 8 + q2;
            float b0 = __ldg(&bs1[c]) + __ldg(&bs2[c]);
            float b1 = __ldg(&bs1[c + 1]) + __ldg(&bs2[c + 1]);
            *(__half2*)&OUT[(size_t)r0 * G4 + c] =
                __floats2half2_rn(acc[mt][nt][0] + b0, acc[mt][nt][1] + b1);
            *(__half2*)&OUT[(size_t)(r0 + 8) * G4 + c] =
                __floats2half2_rn(acc[mt][nt][2] + b0, acc[mt][nt][3] + b1);
        }
    }
}

__device__ __forceinline__ void gbar(unsigned& epoch)
{
    __syncthreads();
    epoch += NCTA;
    if (threadIdx.x == 0) {
        __threadfence();
        atomicAdd(&g_bar, 1u);
        while (*(volatile unsigned*)&g_bar < epoch) { }
        __threadfence();
    }
    __syncthreads();
}

// ---------------- recurrent: 3-deep KC=128, pre-barrier weight prefetch ------
struct RecSmem {
    __half A1[3][64][RPK];
    __half A2[3][64][RPK];
    __half B1s[3][64][RPK];   // streamed [W1(rows 0-31) | U0(rows 32-63)]
    __half U1r[32][PK2];      // resident U1 slice
    float pre[32][66];        // reused: layer1 then layer0
};
#define REC_SMEM_BYTES ((int)sizeof(RecSmem))

__global__ void __launch_bounds__(256, 1)
recur_kernel(float* __restrict__ out)
{
    extern __shared__ unsigned char smraw[];
    RecSmem* sm = (RecSmem*)smraw;

    const int tid = threadIdx.x;
    const int u0 = blockIdx.x * 8;
    const int lane = tid & 31, w = tid >> 5;
    const int g = lane >> 2, q2 = (lane & 3) * 2;
    const int lg = lane >> 3, lr = lane & 7;
    const int cu = tid & 7, cb = tid >> 3;

    const u32 baseA1 = (u32)__cvta_generic_to_shared(&sm->A1[0][0][0]);
    const u32 baseA2 = (u32)__cvta_generic_to_shared(&sm->A2[0][0][0]);
    const u32 baseBs = (u32)__cvta_generic_to_shared(&sm->B1s[0][0][0]);
    const u32 baseU1 = (u32)__cvta_generic_to_shared(&sm->U1r[0][0]);
    const u32 bufstr = 64 * RPK * 2;

    // staging: 12 lines/thread. j 0-3: A1; j 4-7: A2; j 8-11: B1s.
    u32 dstL[12]; size_t offGv[12]; const __half* pWv[4];
#pragma unroll
    for (int j = 0; j < 12; ++j) {
        int lin = tid + j * 256;
        int local = lin & 1023;
        int row = local >> 4, seg = local & 15;
        u32 base = (j < 4) ? baseA1 : ((j < 8) ? baseA2 : baseBs);
        dstL[j] = base + (u32)row * (RPK * 2) + (u32)seg * 16;
        offGv[j] = (size_t)row * HH + seg * 8;
        if (j >= 8) {
            int jj = row & 31;
            int mat = (row < 32) ? 1 : 0;
            pWv[j - 8] = g_Wt + ((size_t)mat * G4 + ((size_t)(jj >> 3) << 10) + u0 + (jj & 7)) * HH
                         + seg * 8;
        }
    }

    const int wlo = (w < 4) ? w : (w - 4);
    const int wm = (wlo >> 1) * 32;
    const int wn = (w < 4) ? ((wlo & 1) * 32) : ((wlo & 1) * 16);

    const u32 offA_0 = (u32)(wm + (lg & 1) * 8 + lr) * (RPK * 2) + (lg >> 1) * 16;
    const u32 offA_1 = offA_0 + 16 * (RPK * 2);
    const u32 offBs_0 = (u32)(wn + (lg >> 1) * 8 + lr) * (RPK * 2) + (lg & 1) * 16;
    const u32 offBs_1 = offBs_0 + 16 * (RPK * 2);
    const u32 offU1  = (u32)(wn + (lg >> 1) * 8 + lr) * (PK2 * 2) + (lg & 1) * 16;

    // resident U1 fill
#pragma unroll
    for (int i = 0; i < 16; ++i) {
        int lin = tid + i * 256;
        int row = lin >> 7, seg = (lin & 127) * 8;
        size_t c = ((size_t)2 * G4 + ((size_t)(row >> 3) << 10) + u0 + (row & 7));
        *(uint4*)&sm->U1r[row][seg] = *(const uint4*)(g_Wt + c * HH + seg);
    }
    float c0r[2] = {0.f, 0.f}, c1r[2] = {0.f, 0.f};
    __syncthreads();
    // prologue: layer0(t=0)
#pragma unroll
    for (int half = 0; half < 2; ++half) {
        int b = cb + half * 32;
        size_t base = ((size_t)b * SS) * G4 + u0 + cu;
        float pi = __half2float(g_P0[base + 1024]);
        float pg = __half2float(g_P0[base + 2048]);
        float po = __half2float(g_P0[base + 3072]);
        float cn = sigf(pi) * tanha(pg);
        c0r[half] = cn;
        g_h0[0][b * HH + u0 + cu] = __float2half(sigf(po) * tanha(cn));
    }
    // G0: chunk0 weights (t-invariant) issued BEFORE the barrier
#pragma unroll
    for (int j = 8; j < 12; ++j) cpa16u(dstL[j], pWv[j - 8]);
    CP_COMMIT();
    unsigned epoch = 0;
    gbar(epoch);

    for (int t = 0; t < SS; ++t) {
        const __half* h0r = g_h0[t & 1];
        const __half* h1r = g_h1[(t + 1) & 1];
        __half* h0w = g_h0[(t + 1) & 1];
        __half* h1w = g_h1[t & 1];

        // G1: chunk0 A-halves (h-dependent)
#pragma unroll
        for (int j = 0; j < 4; ++j) cpa16u(dstL[j], h0r + offGv[j]);
#pragma unroll
        for (int j = 4; j < 8; ++j) cpa16u(dstL[j], h1r + offGv[j]);
        CP_COMMIT();
        // G2: chunk1 (full)
        {
            const u32 bo = bufstr;
#pragma unroll
            for (int j = 0; j < 4; ++j) cpa16u(dstL[j] + bo, h0r + offGv[j] + RKC);
#pragma unroll
            for (int j = 4; j < 8; ++j) cpa16u(dstL[j] + bo, h1r + offGv[j] + RKC);
#pragma unroll
            for (int j = 8; j < 12; ++j) cpa16u(dstL[j] + bo, pWv[j - 8] + RKC);
            CP_COMMIT();
        }

        // ---- P prefetch (half2) into registers ----
        float2 pP[2][4][2];
        const bool isL1p = (w < 4) && (wn == 0);
        const bool isL0p = (w < 4) && (wn != 0) && (t < SS - 1);
        if (isL1p || isL0p) {
            const __half* Pb = isL1p ? g_P1 : g_P0;
            const int tt = isL1p ? t : t + 1;
#pragma unroll
            for (int mt = 0; mt < 2; ++mt) {
                int r0 = wm + mt * 16 + g;
#pragma unroll
                for (int nt = 0; nt < 4; ++nt) {
                    int cj = nt * 8 + q2;
                    int gate = cj >> 3, un = cj & 7;
                    const __half* base = Pb + ((size_t)gate << 10) + u0 + un;
                    pP[mt][nt][0] = __half22float2(
                        *(const __half2*)(base + ((size_t)r0 * SS + tt) * G4));
                    pP[mt][nt][1] = __half22float2(
                        *(const __half2*)(base + ((size_t)(r0 + 8) * SS + tt) * G4));
                }
            }
        }

        float acc[2][4][4];
#pragma unroll
        for (int a = 0; a < 2; ++a)
#pragma unroll
            for (int b = 0; b < 4; ++b)
#pragma unroll
                for (int c = 0; c < 4; ++c) acc[a][b][c] = 0.f;

        for (int ch = 0; ch < RNCH; ++ch) {
            // issue chunk ch+2 (its buffer (ch+2)%3 was freed after compute ch-1)
            if (ch + 2 < RNCH) {
                const u32 bo = (u32)((ch + 2) % 3) * bufstr;
                const int kc = (ch + 2) * RKC;
#pragma unroll
                for (int j = 0; j < 4; ++j) cpa16u(dstL[j] + bo, h0r + offGv[j] + kc);
#pragma unroll
                for (int j = 4; j < 8; ++j) cpa16u(dstL[j] + bo, h1r + offGv[j] + kc);
#pragma unroll
                for (int j = 8; j < 12; ++j) cpa16u(dstL[j] + bo, pWv[j - 8] + kc);
                CP_COMMIT();
            }
            // wait for chunk ch's data (allow groups of chunks ch+1, ch+2)
            if (ch + 2 < RNCH)      asm volatile("cp.async.wait_group 2;\n" ::: "memory");
            else if (ch + 1 < RNCH) asm volatile("cp.async.wait_group 1;\n" ::: "memory");
            else                    asm volatile("cp.async.wait_group 0;\n" ::: "memory");
            __syncthreads();

            const u32 boA = (u32)(ch % 3) * bufstr;
            const u32 kgl2 = (u32)(ch * RKC) * 2;
            if (w < 4) {
#pragma unroll
                for (int kk = 0; kk < 8; ++kk) {
                    const u32 kb2 = kk * 32;
                    u32 a[2][4], bA[4], bB[4];
                    ldsm4(a[0][0], a[0][1], a[0][2], a[0][3], baseA1 + boA + offA_0 + kb2);
                    ldsm4(a[1][0], a[1][1], a[1][2], a[1][3], baseA1 + boA + offA_1 + kb2);
                    ldsm4(bA[0], bA[1], bA[2], bA[3], baseBs + boA + offBs_0 + kb2);
                    ldsm4(bB[0], bB[1], bB[2], bB[3], baseBs + boA + offBs_1 + kb2);
#pragma unroll
                    for (int nt = 0; nt < 4; ++nt) {
                        u32 b0 = (nt < 2) ? bA[(nt & 1) * 2]     : bB[(nt & 1) * 2];
                        u32 b1 = (nt < 2) ? bA[(nt & 1) * 2 + 1] : bB[(nt & 1) * 2 + 1];
                        mma_h(acc[0][nt], a[0][0], a[0][1], a[0][2], a[0][3], b0, b1);
                        mma_h(acc[1][nt], a[1][0], a[1][1], a[1][2], a[1][3], b0, b1);
                    }
                }
            } else {
#pragma unroll
                for (int kk = 0; kk < 8; ++kk) {
                    const u32 kb2 = kk * 32;
                    u32 a[2][4], bA[4];
                    ldsm4(a[0][0], a[0][1], a[0][2], a[0][3], baseA2 + boA + offA_0 + kb2);
                    ldsm4(a[1][0], a[1][1], a[1][2], a[1][3], baseA2 + boA + offA_1 + kb2);
                    ldsm4(bA[0], bA[1], bA[2], bA[3], baseU1 + offU1 + kgl2 + kb2);
#pragma unroll
                    for (int nt = 0; nt < 2; ++nt) {
                        u32 b0 = bA[nt * 2], b1 = bA[nt * 2 + 1];
                        mma_h(acc[0][nt], a[0][0], a[0][1], a[0][2], a[0][3], b0, b1);
                        mma_h(acc[1][nt], a[1][0], a[1][1], a[1][2], a[1][3], b0, b1);
                    }
                }
            }
        }

        // ---- epilogue stage 1: layer1 main (wn==0 warps: h0@W1 + P1) ----
        if (w < 4 && wn == 0) {
#pragma unroll
            for (int mt = 0; mt < 2; ++mt) {
                int r0 = wm + mt * 16 + g;
#pragma unroll
                for (int nt = 0; nt < 4; ++nt) {
                    int cj = nt * 8 + q2;
                    sm->pre[cj][r0]         = acc[mt][nt][0] + pP[mt][nt][0].x;
                    sm->pre[cj + 1][r0]     = acc[mt][nt][1] + pP[mt][nt][0].y;
                    sm->pre[cj][r0 + 8]     = acc[mt][nt][2] + pP[mt][nt][1].x;
                    sm->pre[cj + 1][r0 + 8] = acc[mt][nt][3] + pP[mt][nt][1].y;
                }
            }
        }
        __syncthreads();
        // ---- stage 2: U1 add (warps 4-7) ----
        if (w >= 4) {
#pragma unroll
            for (int mt = 0; mt < 2; ++mt) {
                int r0 = wm + mt * 16 + g;
#pragma unroll
                for (int nt = 0; nt < 2; ++nt) {
                    int cj = wn + nt * 8 + q2;
                    sm->pre[cj][r0]         += acc[mt][nt][0];
                    sm->pre[cj + 1][r0]     += acc[mt][nt][1];
                    sm->pre[cj][r0 + 8]     += acc[mt][nt][2];
                    sm->pre[cj + 1][r0 + 8] += acc[mt][nt][3];
                }
            }
        }
        __syncthreads();
        // ---- cells layer 1 ----
#pragma unroll
        for (int half = 0; half < 2; ++half) {
            int b = cb + half * 32;
            float f  = sigf(sm->pre[cu][b]);
            float ii = sigf(sm->pre[8 + cu][b]);
            float gg = tanha(sm->pre[16 + cu][b]);
            float oo = sigf(sm->pre[24 + cu][b]);
            float cn = f * c1r[half] + ii * gg;
            c1r[half] = cn;
            float h = oo * tanha(cn);
            h1w[b * HH + u0 + cu] = __float2half(h);
            g_Hout[((size_t)b * SS + t) * HH + u0 + cu] = h;
            if (t == SS - 1) {
                out[98304 + 65536 + b * HH + u0 + cu] = h;
                out[229376 + 65536 + b * HH + u0 + cu] = cn;
            }
        }
        __syncthreads();
        // ---- stage 3: layer0 pre (wn==32 warps: h0@U0 + P0[t+1]) ----
        if (w < 4 && wn == 32 && t < SS - 1) {
#pragma unroll
            for (int mt = 0; mt < 2; ++mt) {
                int r0 = wm + mt * 16 + g;
#pragma unroll
                for (int nt = 0; nt < 4; ++nt) {
                    int cj = nt * 8 + q2;
                    sm->pre[cj][r0]         = acc[mt][nt][0] + pP[mt][nt][0].x;
                    sm->pre[cj + 1][r0]     = acc[mt][nt][1] + pP[mt][nt][0].y;
                    sm->pre[cj][r0 + 8]     = acc[mt][nt][2] + pP[mt][nt][1].x;
                    sm->pre[cj + 1][r0 + 8] = acc[mt][nt][3] + pP[mt][nt][1].y;
                }
            }
        }
        __syncthreads();
        // ---- cells layer 0 ----
        if (t < SS - 1) {
#pragma unroll
            for (int half = 0; half < 2; ++half) {
                int b = cb + half * 32;
                float f  = sigf(sm->pre[cu][b]);
                float ii = sigf(sm->pre[8 + cu][b]);
                float gg = tanha(sm->pre[16 + cu][b]);
                float oo = sigf(sm->pre[24 + cu][b]);
                float cn = f * c0r[half] + ii * gg;
                c0r[half] = cn;
                float h = oo * tanha(cn);
                h0w[b * HH + u0 + cu] = __float2half(h);
                if (t == SS - 2) {
                    out[98304 + b * HH + u0 + cu] = h;
                    out[229376 + b * HH + u0 + cu] = cn;
                }
            }
        }
        // G0 for next step: chunk0 weights, issued before the barrier
        if (t < SS - 1) {
#pragma unroll
            for (int j = 8; j < 12; ++j) cpa16u(dstL[j], pWv[j - 8]);
        }
        CP_COMMIT();
        gbar(epoch);
    }
}

__global__ void __launch_bounds__(256)
head_kernel(const float* __restrict__ fcW, const float* __restrict__ fcb,
            float* __restrict__ out)
{
    int warp = (blockIdx.x * blockDim.x + threadIdx.x) >> 5;
    int lane = threadIdx.x & 31;
    if (warp >= BB * SS) return;
    const float* hrow = &g_Hout[(size_t)warp * HH];
    float a0 = 0.f, a1 = 0.f, a2 = 0.f;
    for (int k = lane; k < HH; k += 32) {
        float h = __ldg(&hrow[k]);
        a0 += h * __ldg(&fcW[k * 3 + 0]);
        a1 += h * __ldg(&fcW[k * 3 + 1]);
        a2 += h * __ldg(&fcW[k * 3 + 2]);
    }
#pragma unroll
    for (int off = 16; off; off >>= 1) {
        a0 += __shfl_xor_sync(0xffffffffu, a0, off);
        a1 += __shfl_xor_sync(0xffffffffu, a1, off);
        a2 += __shfl_xor_sync(0xffffffffu, a2, off);
    }
    if (lane == 0) {
        out[warp * 3 + 0] = a0 + __ldg(&fcb[0]);
        out[warp * 3 + 1] = a1 + __ldg(&fcb[1]);
        out[warp * 3 + 2] = a2 + __ldg(&fcb[2]);
    }
}

extern "C" void kernel_launch(void* const* d_in, const int* in_sizes, int n_in,
                              void* d_out, int out_size)
{
    const float* x    = (const float*)d_in[0];
    const float* z    = (const float*)d_in[1];
    const float* W0   = (const float*)d_in[2];
    const float* bW0  = (const float*)d_in[3];
    const float* U0   = (const float*)d_in[4];
    const float* V0   = (const float*)d_in[5];
    const float* b0   = (const float*)d_in[6];
    const float* W1   = (const float*)d_in[7];
    const float* bW1  = (const float*)d_in[8];
    const float* U1   = (const float*)d_in[9];
    const float* V1   = (const float*)d_in[10];
    const float* b1   = (const float*)d_in[11];
    const float* fcW  = (const float*)d_in[12];
    const float* fcb  = (const float*)d_in[13];
    float* out = (float*)d_out;

    static int smem_set = 0;
    if (!smem_set) {
        cudaFuncSetAttribute(recur_kernel, cudaFuncAttributeMaxDynamicSharedMemorySize,
                             REC_SMEM_BYTES);
        cudaFuncSetAttribute(gemm_mma_kernel, cudaFuncAttributeMaxDynamicSharedMemorySize,
                             G_SMEM_BYTES);
        smem_set = 1;
    }

    prep2a_kernel<<<2048, 256>>>(x, z);
    prep_all_kernel<<<dim3(64, 16, 6), 256>>>(U0, W1, U1, W0, V0, V1);
    gemm_mma_kernel<<<dim3(64, 512, 2), 256, G_SMEM_BYTES>>>(bW0, b0, bW1, b1);
    recur_kernel<<<NCTA, 256, REC_SMEM_BYTES>>>(out);
    head_kernel<<<4096, 256>>>(fcW, fcb, out);
}